// round 3
// baseline (speedup 1.0000x reference)
#include <cuda_runtime.h>
#include <math.h>

#define BB   4
#define SS   2048
#define HH   8
#define DHH  32
#define DIMM 256
#define NB   512          // SS / 4 compressed blocks
#define BS   (BB*SS)      // 8192 rows
#define BSD  (BS*DIMM)    // 2097152 floats
#define QT   256          // queries per attn block
#define NQT  (SS/QT)      // 8 qtiles

// ---------------- scratch (static device buffers; no allocs) ----------------
__device__ float g_h  [BSD];
__device__ float g_q  [BSD];
__device__ float g_k  [BSD];
__device__ float g_v  [BSD];
__device__ float g_o  [BSD];
__device__ float g_g  [BS*24];
__device__ float g_kc [BB*HH*DHH*NB];
__device__ float g_vc [BB*HH*DHH*NB];
__device__ float g_mid[BS*512];

// ---------------- LayerNorm: one warp per row of 256 ----------------
__global__ void ln_kernel(const float* __restrict__ x, const float* __restrict__ gw,
                          const float* __restrict__ bw, float* __restrict__ out)
{
    int warp = (blockIdx.x * blockDim.x + threadIdx.x) >> 5;
    int lane = threadIdx.x & 31;
    if (warp >= BS) return;
    const float* xr = x + (size_t)warp * DIMM;
    float vbuf[8];
    float s = 0.f;
    #pragma unroll
    for (int i = 0; i < 8; i++) { vbuf[i] = xr[lane + i*32]; s += vbuf[i]; }
    #pragma unroll
    for (int o = 16; o > 0; o >>= 1) s += __shfl_xor_sync(~0u, s, o);
    float m = s * (1.f/256.f);
    float sq = 0.f;
    #pragma unroll
    for (int i = 0; i < 8; i++) { float d = vbuf[i] - m; sq += d*d; }
    #pragma unroll
    for (int o = 16; o > 0; o >>= 1) sq += __shfl_xor_sync(~0u, sq, o);
    float rstd = rsqrtf(sq * (1.f/256.f) + 1e-5f);
    float* orow = out + (size_t)warp * DIMM;
    #pragma unroll
    for (int i = 0; i < 8; i++) {
        int c = lane + i*32;
        orow[c] = (vbuf[i] - m) * rstd * gw[c] + bw[c];
    }
}

// ---------------- small GEMM for gate (N=24), sigmoid epilogue ----------------
__global__ void __launch_bounds__(256) gate_gemm_kernel(
    const float* __restrict__ A, const float* __restrict__ B,
    float* __restrict__ C, int M, int N, int K)
{
    __shared__ float As[16][65];
    __shared__ float Bs[16][65];
    int tid = threadIdx.x;
    int tx = tid & 15, ty = tid >> 4;
    int bm = blockIdx.y << 6, bn = blockIdx.x << 6;
    float acc[4][4];
    #pragma unroll
    for (int i = 0; i < 4; i++)
        #pragma unroll
        for (int j = 0; j < 4; j++) acc[i][j] = 0.f;

    for (int k0 = 0; k0 < K; k0 += 16) {
        #pragma unroll
        for (int i = 0; i < 4; i++) {
            int e = tid + (i << 8);
            int r = e >> 4, kk = e & 15;
            As[kk][r] = A[(size_t)(bm + r)*K + k0 + kk];
        }
        #pragma unroll
        for (int i = 0; i < 4; i++) {
            int e = tid + (i << 8);
            int kk = e >> 6, c = e & 63;
            Bs[kk][c] = (bn + c < N) ? B[(size_t)(k0 + kk)*N + bn + c] : 0.f;
        }
        __syncthreads();
        #pragma unroll
        for (int kk = 0; kk < 16; kk++) {
            float a[4], bb[4];
            #pragma unroll
            for (int i = 0; i < 4; i++) a[i] = As[kk][(ty<<2)+i];
            #pragma unroll
            for (int j = 0; j < 4; j++) bb[j] = Bs[kk][(tx<<2)+j];
            #pragma unroll
            for (int i = 0; i < 4; i++)
                #pragma unroll
                for (int j = 0; j < 4; j++)
                    acc[i][j] = fmaf(a[i], bb[j], acc[i][j]);
        }
        __syncthreads();
    }
    #pragma unroll
    for (int i = 0; i < 4; i++) {
        int row = bm + (ty<<2) + i;
        #pragma unroll
        for (int j = 0; j < 4; j++) {
            int col = bn + (tx<<2) + j;
            if (col >= N) continue;
            C[(size_t)row * N + col] = 1.f / (1.f + expf(-acc[i][j]));
        }
    }
}

// ---------------- main GEMM: 64x128 tile, BK=16, 4x8 micro, double-buffered ----
// requires M%64==0, N%128==0, K%16==0
// EPI: 0=store  2=bias+leakyrelu  3=C+=val+bias  4=C+=val
// QKV=true: blockIdx.z in {0,1,2} selects (B0,C0)/(B1,C1)/(B2,C2)
template<int EPI, bool QKV>
__global__ void __launch_bounds__(256) gemm64_kernel(
    const float* __restrict__ A,
    const float* __restrict__ B0, const float* __restrict__ B1, const float* __restrict__ B2,
    const float* __restrict__ bias,
    float* __restrict__ C0, float* __restrict__ C1, float* __restrict__ C2,
    int M, int N, int K)
{
    __shared__ float As[2][16][68];
    __shared__ float Bs[2][16][128];

    const float* B = B0;
    float* C = C0;
    if (QKV) {
        if (blockIdx.z == 1)      { B = B1; C = C1; }
        else if (blockIdx.z == 2) { B = B2; C = C2; }
    }

    int tid = threadIdx.x;
    int tx = tid & 15, ty = tid >> 4;
    int bm = blockIdx.y << 6, bn = blockIdx.x << 7;

    int ar  = tid >> 2, akq = tid & 3;          // A loader: row, k-quad
    int bkk = tid >> 5, bcq = tid & 31;         // B loader: kk (0..7), col-quad

    float acc[4][8];
    #pragma unroll
    for (int i = 0; i < 4; i++)
        #pragma unroll
        for (int j = 0; j < 8; j++) acc[i][j] = 0.f;

    const float* Aptr = A + (size_t)(bm + ar)*K + (akq << 2);
    const float* Bptr = B + (size_t)bkk*N + bn + (bcq << 2);

    // prologue: tile 0 -> buffer 0
    float4 a4 = *(const float4*)Aptr;
    float4 bA = *(const float4*)Bptr;
    float4 bB = *(const float4*)(Bptr + (size_t)8*N);
    As[0][(akq<<2)+0][ar] = a4.x;
    As[0][(akq<<2)+1][ar] = a4.y;
    As[0][(akq<<2)+2][ar] = a4.z;
    As[0][(akq<<2)+3][ar] = a4.w;
    *(float4*)&Bs[0][bkk    ][bcq<<2] = bA;
    *(float4*)&Bs[0][bkk + 8][bcq<<2] = bB;
    __syncthreads();

    int T = K >> 4;
    for (int kt = 0; kt < T; kt++) {
        int cur = kt & 1;
        if (kt < T - 1) {
            int k0 = (kt + 1) << 4;
            a4 = *(const float4*)(Aptr + k0);
            bA = *(const float4*)(Bptr + (size_t)k0*N);
            bB = *(const float4*)(Bptr + (size_t)(k0 + 8)*N);
        }
        #pragma unroll
        for (int kk = 0; kk < 16; kk++) {
            float4 av = *(const float4*)&As[cur][kk][ty << 2];
            float4 b0 = *(const float4*)&Bs[cur][kk][tx << 3];
            float4 b1 = *(const float4*)&Bs[cur][kk][(tx << 3) + 4];
            float a_[4] = {av.x, av.y, av.z, av.w};
            float b_[8] = {b0.x, b0.y, b0.z, b0.w, b1.x, b1.y, b1.z, b1.w};
            #pragma unroll
            for (int i = 0; i < 4; i++)
                #pragma unroll
                for (int j = 0; j < 8; j++)
                    acc[i][j] = fmaf(a_[i], b_[j], acc[i][j]);
        }
        if (kt < T - 1) {
            int nxt = cur ^ 1;
            As[nxt][(akq<<2)+0][ar] = a4.x;
            As[nxt][(akq<<2)+1][ar] = a4.y;
            As[nxt][(akq<<2)+2][ar] = a4.z;
            As[nxt][(akq<<2)+3][ar] = a4.w;
            *(float4*)&Bs[nxt][bkk    ][bcq<<2] = bA;
            *(float4*)&Bs[nxt][bkk + 8][bcq<<2] = bB;
            __syncthreads();
        }
    }

    #pragma unroll
    for (int i = 0; i < 4; i++) {
        int row = bm + (ty << 2) + i;
        float* crow = C + (size_t)row * N + bn + (tx << 3);
        if (EPI == 0) {
            float4 o0, o1;
            o0.x = acc[i][0]; o0.y = acc[i][1]; o0.z = acc[i][2]; o0.w = acc[i][3];
            o1.x = acc[i][4]; o1.y = acc[i][5]; o1.z = acc[i][6]; o1.w = acc[i][7];
            *(float4*)crow = o0;
            *(float4*)(crow + 4) = o1;
        } else {
            #pragma unroll
            for (int j = 0; j < 8; j++) {
                int col = bn + (tx << 3) + j;
                float val = acc[i][j];
                if (EPI == 2)      { float z = val + bias[col]; crow[j] = z > 0.f ? z : 0.01f*z; }
                else if (EPI == 3) crow[j] += val + bias[col];
                else if (EPI == 4) crow[j] += val;
            }
        }
    }
}

// ---------------- KV mean-pool into transposed [B,H,DH,NB] layout ----------------
__global__ void pool_kernel(const float* __restrict__ k, const float* __restrict__ v,
                            float* __restrict__ kc, float* __restrict__ vc)
{
    int wid = (blockIdx.x * blockDim.x + threadIdx.x) >> 5;  // [0, B*H*NB)
    int lane = threadIdx.x & 31;
    if (wid >= BB*HH*NB) return;
    int n = wid % NB;
    int h = (wid / NB) % HH;
    int b = wid / (NB*HH);
    float sk = 0.f, sv = 0.f;
    #pragma unroll
    for (int c = 0; c < 4; c++) {
        size_t idx = ((size_t)(b*SS + n*4 + c)*HH + h)*DHH + lane;
        sk += k[idx]; sv += v[idx];
    }
    size_t oidx = ((size_t)(b*HH + h)*DHH + lane)*NB + n;
    kc[oidx] = sk * 0.25f;
    vc[oidx] = sv * 0.25f;
}

// ---------------- fused NSA attention: one THREAD per (b,h,t), tiled kc/vc in smem ----------------
__global__ void __launch_bounds__(256) nsa_attn_kernel(
    const float* __restrict__ q, const float* __restrict__ k, const float* __restrict__ v,
    const float* __restrict__ kc, const float* __restrict__ vc,
    const float* __restrict__ g, float* __restrict__ o)
{
    __shared__ float kcs[32][64];
    __shared__ float vcs[32][64];

    int tid   = threadIdx.x;
    int qtile = blockIdx.x & (NQT - 1);
    int h     = (blockIdx.x / NQT) & (HH - 1);
    int b     = blockIdx.x / (NQT * HH);
    int t     = qtile * QT + tid;

    const float SCALE = 0.17677669529663687f;  // 32^-0.5
    float qv[32];
    {
        const float4* qr = (const float4*)(q + ((size_t)(b*SS + t)*HH + h)*DHH);
        #pragma unroll
        for (int i = 0; i < 8; i++) {
            float4 f = qr[i];
            qv[4*i+0] = f.x * SCALE; qv[4*i+1] = f.y * SCALE;
            qv[4*i+2] = f.z * SCALE; qv[4*i+3] = f.w * SCALE;
        }
    }

    int own = t >> 2;
    const float* kcb = kc + (size_t)(b*HH + h)*DHH*NB;
    const float* vcb = vc + (size_t)(b*HH + h)*DHH*NB;

    float Ml = -INFINITY, Z = 0.f;
    float av[32];
    #pragma unroll
    for (int j = 0; j < 32; j++) av[j] = 0.f;
    float bval = -INFINITY; int bidx = NB;

    for (int tile = 0; tile <= qtile; tile++) {
        int n0 = tile << 6;
        if (tile) __syncthreads();
        #pragma unroll
        for (int i = 0; i < 8; i++) {
            int idx = tid + (i << 8);
            int kk = idx >> 6, n = idx & 63;
            kcs[kk][n] = kcb[kk*NB + n0 + n];
            vcs[kk][n] = vcb[kk*NB + n0 + n];
        }
        __syncthreads();

        int lim = (tile == qtile) ? ((tid + 1) >> 2) : 64;

        for (int n4 = 0; n4 < 64; n4 += 4) {
            if (n4 >= lim) break;
            float s0 = 0.f, s1 = 0.f, s2 = 0.f, s3 = 0.f;
            #pragma unroll
            for (int kk = 0; kk < 32; kk++) {
                float4 kf = *(const float4*)&kcs[kk][n4];
                s0 = fmaf(qv[kk], kf.x, s0);
                s1 = fmaf(qv[kk], kf.y, s1);
                s2 = fmaf(qv[kk], kf.z, s2);
                s3 = fmaf(qv[kk], kf.w, s3);
            }
            if (n4 + 1 >= lim) s1 = -INFINITY;
            if (n4 + 2 >= lim) s2 = -INFINITY;
            if (n4 + 3 >= lim) s3 = -INFINITY;

            int gn = n0 + n4;
            if (gn + 0 != own && s0 > bval) { bval = s0; bidx = gn + 0; }
            if (gn + 1 != own && s1 > bval) { bval = s1; bidx = gn + 1; }
            if (gn + 2 != own && s2 > bval) { bval = s2; bidx = gn + 2; }
            if (gn + 3 != own && s3 > bval) { bval = s3; bidx = gn + 3; }

            float m4 = fmaxf(fmaxf(s0, s1), fmaxf(s2, s3));
            if (m4 > Ml) {
                float r = __expf(Ml - m4);
                Z *= r;
                #pragma unroll
                for (int j = 0; j < 32; j++) av[j] *= r;
                Ml = m4;
            }
            float p0 = __expf(s0 - Ml);
            float p1 = __expf(s1 - Ml);
            float p2 = __expf(s2 - Ml);
            float p3 = __expf(s3 - Ml);
            Z += (p0 + p1) + (p2 + p3);
            #pragma unroll
            for (int j = 0; j < 32; j++) {
                float4 vf = *(const float4*)&vcs[j][n4];
                av[j] = fmaf(p0, vf.x, av[j]);
                av[j] = fmaf(p1, vf.y, av[j]);
                av[j] = fmaf(p2, vf.z, av[j]);
                av[j] = fmaf(p3, vf.w, av[j]);
            }
        }
    }

    if (bval == -INFINITY) bidx = (own == 0) ? 1 : 0;

    const float* gr = g + (size_t)(b*SS + t)*24;
    float g0 = gr[h], g1 = gr[8 + h], g2 = gr[16 + h];

    float invZ = (Z > 0.f) ? (1.f / Z) : 0.f;
    float c0 = g0 * invZ;
    #pragma unroll
    for (int j = 0; j < 32; j++) av[j] *= c0;

    // ---- selection branch: blocks {own, bidx}, 8 keys, mask pos<=t ----
    float sc[8];
    float smax = -INFINITY;
    #pragma unroll
    for (int e = 0; e < 8; e++) {
        int pos = ((e < 4) ? own : bidx) * 4 + (e & 3);
        const float4* kr = (const float4*)(k + ((size_t)(b*SS + pos)*HH + h)*DHH);
        float s = 0.f;
        #pragma unroll
        for (int i = 0; i < 8; i++) {
            float4 kf = kr[i];
            s = fmaf(qv[4*i+0], kf.x, s);
            s = fmaf(qv[4*i+1], kf.y, s);
            s = fmaf(qv[4*i+2], kf.z, s);
            s = fmaf(qv[4*i+3], kf.w, s);
        }
        s = (pos <= t) ? s : -INFINITY;
        sc[e] = s;
        smax = fmaxf(smax, s);
    }
    float zf = 0.f;
    #pragma unroll
    for (int e = 0; e < 8; e++) { sc[e] = __expf(sc[e] - smax); zf += sc[e]; }
    float c1 = g1 / zf;
    #pragma unroll
    for (int e = 0; e < 8; e++) {
        int pos = ((e < 4) ? own : bidx) * 4 + (e & 3);
        float w = sc[e] * c1;
        const float4* vr = (const float4*)(v + ((size_t)(b*SS + pos)*HH + h)*DHH);
        #pragma unroll
        for (int i = 0; i < 8; i++) {
            float4 vf = vr[i];
            av[4*i+0] = fmaf(w, vf.x, av[4*i+0]);
            av[4*i+1] = fmaf(w, vf.y, av[4*i+1]);
            av[4*i+2] = fmaf(w, vf.z, av[4*i+2]);
            av[4*i+3] = fmaf(w, vf.w, av[4*i+3]);
        }
    }

    // ---- sliding-window branch: keys {t-1, t} ----
    int tp = (t > 0) ? t - 1 : 0;
    float s1w = 0.f, s0w = 0.f;
    {
        const float4* kr1 = (const float4*)(k + ((size_t)(b*SS + t )*HH + h)*DHH);
        const float4* kr0 = (const float4*)(k + ((size_t)(b*SS + tp)*HH + h)*DHH);
        #pragma unroll
        for (int i = 0; i < 8; i++) {
            float4 k1 = kr1[i], k0 = kr0[i];
            s1w = fmaf(qv[4*i+0], k1.x, s1w); s0w = fmaf(qv[4*i+0], k0.x, s0w);
            s1w = fmaf(qv[4*i+1], k1.y, s1w); s0w = fmaf(qv[4*i+1], k0.y, s0w);
            s1w = fmaf(qv[4*i+2], k1.z, s1w); s0w = fmaf(qv[4*i+2], k0.z, s0w);
            s1w = fmaf(qv[4*i+3], k1.w, s1w); s0w = fmaf(qv[4*i+3], k0.w, s0w);
        }
    }
    if (t == 0) s0w = -INFINITY;
    float wm = fmaxf(s0w, s1w);
    float p0w = __expf(s0w - wm), p1w = __expf(s1w - wm);
    float c2 = g2 / (p0w + p1w);
    float w0 = p0w * c2, w1 = p1w * c2;
    {
        const float4* vr1 = (const float4*)(v + ((size_t)(b*SS + t )*HH + h)*DHH);
        const float4* vr0 = (const float4*)(v + ((size_t)(b*SS + tp)*HH + h)*DHH);
        #pragma unroll
        for (int i = 0; i < 8; i++) {
            float4 v1 = vr1[i], v0 = vr0[i];
            av[4*i+0] = fmaf(w1, v1.x, fmaf(w0, v0.x, av[4*i+0]));
            av[4*i+1] = fmaf(w1, v1.y, fmaf(w0, v0.y, av[4*i+1]));
            av[4*i+2] = fmaf(w1, v1.z, fmaf(w0, v0.z, av[4*i+2]));
            av[4*i+3] = fmaf(w1, v1.w, fmaf(w0, v0.w, av[4*i+3]));
        }
    }

    float4* orow = (float4*)(o + ((size_t)(b*SS + t)*HH + h)*DHH);
    #pragma unroll
    for (int i = 0; i < 8; i++) {
        float4 f;
        f.x = av[4*i+0]; f.y = av[4*i+1]; f.z = av[4*i+2]; f.w = av[4*i+3];
        orow[i] = f;
    }
}

// ---------------- host orchestration ----------------
extern "C" void kernel_launch(void* const* d_in, const int* in_sizes, int n_in,
                              void* d_out, int out_size)
{
    const float* x_in   = (const float*)d_in[0];
    const float* ln_a_g = (const float*)d_in[1];
    const float* ln_a_b = (const float*)d_in[2];
    const float* Wq     = (const float*)d_in[3];
    const float* Wk     = (const float*)d_in[4];
    const float* Wv     = (const float*)d_in[5];
    const float* Wg     = (const float*)d_in[6];
    const float* Wo     = (const float*)d_in[7];
    const float* ln_f_g = (const float*)d_in[8];
    const float* ln_f_b = (const float*)d_in[9];
    const float* W1     = (const float*)d_in[10];
    const float* b1     = (const float*)d_in[11];
    const float* W2     = (const float*)d_in[12];
    const float* b2     = (const float*)d_in[13];
    float* x = (float*)d_out;

    float *ph, *pq, *pk, *pv, *po, *pg, *pkc, *pvc, *pmid;
    cudaGetSymbolAddress((void**)&ph,   g_h);
    cudaGetSymbolAddress((void**)&pq,   g_q);
    cudaGetSymbolAddress((void**)&pk,   g_k);
    cudaGetSymbolAddress((void**)&pv,   g_v);
    cudaGetSymbolAddress((void**)&po,   g_o);
    cudaGetSymbolAddress((void**)&pg,   g_g);
    cudaGetSymbolAddress((void**)&pkc,  g_kc);
    cudaGetSymbolAddress((void**)&pvc,  g_vc);
    cudaGetSymbolAddress((void**)&pmid, g_mid);

    cudaMemcpyAsync(x, x_in, (size_t)BSD * sizeof(float), cudaMemcpyDeviceToDevice, 0);

    for (int l = 0; l < 2; l++) {
        for (int j2 = 0; j2 < 2; j2++) {
            int li = l*2 + j2;
            ln_kernel<<<BS/8, 256>>>(x, ln_a_g + li*DIMM, ln_a_b + li*DIMM, ph);
            // fused Q/K/V projections: one launch, z selects weight/output
            gemm64_kernel<0, true><<<dim3(2, 128, 3), 256>>>(
                ph,
                Wq + (size_t)li*DIMM*DIMM, Wk + (size_t)li*DIMM*DIMM, Wv + (size_t)li*DIMM*DIMM,
                nullptr, pq, pk, pv, BS, DIMM, DIMM);
            gate_gemm_kernel<<<dim3(1, BS/64), 256>>>(ph, Wg + (size_t)li*DIMM*24, pg, BS, 24, DIMM);
            pool_kernel<<<(BB*HH*NB*32)/256, 256>>>(pk, pv, pkc, pvc);
            nsa_attn_kernel<<<BB*HH*NQT, 256>>>(pq, pk, pv, pkc, pvc, pg, po);
            gemm64_kernel<4, false><<<dim3(2, 128), 256>>>(
                po, Wo + (size_t)li*DIMM*DIMM, nullptr, nullptr,
                nullptr, x, nullptr, nullptr, BS, DIMM, DIMM);
        }
        ln_kernel<<<BS/8, 256>>>(x, ln_f_g + l*DIMM, ln_f_b + l*DIMM, ph);
        gemm64_kernel<2, false><<<dim3(4, 128), 256>>>(
            ph, W1 + (size_t)l*DIMM*512, nullptr, nullptr,
            b1 + l*512, pmid, nullptr, nullptr, BS, 512, DIMM);
        gemm64_kernel<3, false><<<dim3(2, 128), 256>>>(
            pmid, W2 + (size_t)l*512*DIMM, nullptr, nullptr,
            b2 + l*DIMM, x, nullptr, nullptr, BS, DIMM, 512);
    }
}

// round 4
// speedup vs baseline: 1.1885x; 1.1885x over previous
#include <cuda_runtime.h>
#include <math.h>

#define BB   4
#define SS   2048
#define HH   8
#define DHH  32
#define DIMM 256
#define NB   512          // SS / 4 compressed blocks
#define BS   (BB*SS)      // 8192 rows
#define BSD  (BS*DIMM)    // 2097152 floats
#define QT   256          // queries per attn block
#define NQT  (SS/QT)      // 8 qtiles

// ---------------- scratch (static device buffers; no allocs) ----------------
__device__ float g_h  [BSD];
__device__ float g_q  [BSD];
__device__ float g_k  [BSD];
__device__ float g_v  [BSD];
__device__ float g_o  [BSD];
__device__ float g_g  [BS*24];
__device__ float g_kc [BB*HH*DHH*NB];
__device__ float g_vc [BB*HH*DHH*NB];
__device__ float g_mid[BS*512];

__device__ __forceinline__ void cp_async16(void* smem, const void* gmem) {
    unsigned saddr = (unsigned)__cvta_generic_to_shared(smem);
    asm volatile("cp.async.ca.shared.global [%0], [%1], 16;\n" :: "r"(saddr), "l"(gmem));
}
#define CP_COMMIT() asm volatile("cp.async.commit_group;\n" ::: "memory")
#define CP_WAIT0()  asm volatile("cp.async.wait_group 0;\n" ::: "memory")

// ---------------- LayerNorm: one warp per row of 256 ----------------
__global__ void ln_kernel(const float* __restrict__ x, const float* __restrict__ gw,
                          const float* __restrict__ bw, float* __restrict__ out)
{
    int warp = (blockIdx.x * blockDim.x + threadIdx.x) >> 5;
    int lane = threadIdx.x & 31;
    if (warp >= BS) return;
    const float* xr = x + (size_t)warp * DIMM;
    float vbuf[8];
    float s = 0.f;
    #pragma unroll
    for (int i = 0; i < 8; i++) { vbuf[i] = xr[lane + i*32]; s += vbuf[i]; }
    #pragma unroll
    for (int o = 16; o > 0; o >>= 1) s += __shfl_xor_sync(~0u, s, o);
    float m = s * (1.f/256.f);
    float sq = 0.f;
    #pragma unroll
    for (int i = 0; i < 8; i++) { float d = vbuf[i] - m; sq += d*d; }
    #pragma unroll
    for (int o = 16; o > 0; o >>= 1) sq += __shfl_xor_sync(~0u, sq, o);
    float rstd = rsqrtf(sq * (1.f/256.f) + 1e-5f);
    float* orow = out + (size_t)warp * DIMM;
    #pragma unroll
    for (int i = 0; i < 8; i++) {
        int c = lane + i*32;
        orow[c] = (vbuf[i] - m) * rstd * gw[c] + bw[c];
    }
}

// ---------------- small GEMM for gate (N=24), sigmoid epilogue ----------------
__global__ void __launch_bounds__(256) gate_gemm_kernel(
    const float* __restrict__ A, const float* __restrict__ B,
    float* __restrict__ C, int M, int N, int K)
{
    __shared__ float As[16][65];
    __shared__ float Bs[16][65];
    int tid = threadIdx.x;
    int tx = tid & 15, ty = tid >> 4;
    int bm = blockIdx.y << 6, bn = blockIdx.x << 6;
    float acc[4][4];
    #pragma unroll
    for (int i = 0; i < 4; i++)
        #pragma unroll
        for (int j = 0; j < 4; j++) acc[i][j] = 0.f;

    for (int k0 = 0; k0 < K; k0 += 16) {
        #pragma unroll
        for (int i = 0; i < 4; i++) {
            int e = tid + (i << 8);
            int r = e >> 4, kk = e & 15;
            As[kk][r] = A[(size_t)(bm + r)*K + k0 + kk];
        }
        #pragma unroll
        for (int i = 0; i < 4; i++) {
            int e = tid + (i << 8);
            int kk = e >> 6, c = e & 63;
            Bs[kk][c] = (bn + c < N) ? B[(size_t)(k0 + kk)*N + bn + c] : 0.f;
        }
        __syncthreads();
        #pragma unroll
        for (int kk = 0; kk < 16; kk++) {
            float a[4], bb[4];
            #pragma unroll
            for (int i = 0; i < 4; i++) a[i] = As[kk][(ty<<2)+i];
            #pragma unroll
            for (int j = 0; j < 4; j++) bb[j] = Bs[kk][(tx<<2)+j];
            #pragma unroll
            for (int i = 0; i < 4; i++)
                #pragma unroll
                for (int j = 0; j < 4; j++)
                    acc[i][j] = fmaf(a[i], bb[j], acc[i][j]);
        }
        __syncthreads();
    }
    #pragma unroll
    for (int i = 0; i < 4; i++) {
        int row = bm + (ty<<2) + i;
        #pragma unroll
        for (int j = 0; j < 4; j++) {
            int col = bn + (tx<<2) + j;
            if (col >= N) continue;
            C[(size_t)row * N + col] = 1.f / (1.f + expf(-acc[i][j]));
        }
    }
}

// ---------------- main GEMM: 128x128 tile, BK=16, 8x8 micro, cp.async DB ----
// requires M%128==0, N%128==0, K%16==0
// EPI: 0=store  2=bias+leakyrelu  3=C+=val+bias  4=C+=val
// QKV=true: blockIdx.z in {0,1,2} selects (B0,C0)/(B1,C1)/(B2,C2)
template<int EPI, bool QKV>
__global__ void __launch_bounds__(256, 2) gemm128_kernel(
    const float* __restrict__ A,
    const float* __restrict__ B0, const float* __restrict__ B1, const float* __restrict__ B2,
    const float* __restrict__ bias,
    float* __restrict__ C0, float* __restrict__ C1, float* __restrict__ C2,
    int M, int N, int K)
{
    __shared__ float As[2][16][132];
    __shared__ float Bs[2][16][128];

    const float* B = B0;
    float* C = C0;
    if (QKV) {
        if (blockIdx.z == 1)      { B = B1; C = C1; }
        else if (blockIdx.z == 2) { B = B2; C = C2; }
    }

    int tid = threadIdx.x;
    int tx = tid & 15, ty = tid >> 4;
    int bm = blockIdx.y << 7, bn = blockIdx.x << 7;

    // A loader: 2 float4 per thread: (r, kq) for idx = tid + i*256
    int ar0 = tid >> 2,         akq0 = tid & 3;
    int ar1 = (tid + 256) >> 2, akq1 = tid & 3;        // same kq pattern, rows 64..127
    const float* Ap0 = A + (size_t)(bm + ar0)*K + (akq0 << 2);
    const float* Ap1 = A + (size_t)(bm + ar1)*K + (akq1 << 2);
    // B loader (cp.async): rows kk and kk+8
    int bkk = tid >> 5, bcq = tid & 31;
    const float* Bp = B + (size_t)bkk*N + bn + (bcq << 2);

    float acc[8][8];
    #pragma unroll
    for (int i = 0; i < 8; i++)
        #pragma unroll
        for (int j = 0; j < 8; j++) acc[i][j] = 0.f;

    // ---- prologue: stage 0 ----
    {
        float4 a0 = *(const float4*)Ap0;
        float4 a1 = *(const float4*)Ap1;
        cp_async16(&Bs[0][bkk    ][bcq << 2], Bp);
        cp_async16(&Bs[0][bkk + 8][bcq << 2], Bp + (size_t)8*N);
        CP_COMMIT();
        As[0][(akq0<<2)+0][ar0] = a0.x;
        As[0][(akq0<<2)+1][ar0] = a0.y;
        As[0][(akq0<<2)+2][ar0] = a0.z;
        As[0][(akq0<<2)+3][ar0] = a0.w;
        As[0][(akq1<<2)+0][ar1] = a1.x;
        As[0][(akq1<<2)+1][ar1] = a1.y;
        As[0][(akq1<<2)+2][ar1] = a1.z;
        As[0][(akq1<<2)+3][ar1] = a1.w;
        CP_WAIT0();
        __syncthreads();
    }

    int T = K >> 4;
    for (int kt = 0; kt < T; kt++) {
        int cur = kt & 1, nxt = cur ^ 1;
        float4 a0, a1;
        if (kt < T - 1) {
            int k0 = (kt + 1) << 4;
            a0 = *(const float4*)(Ap0 + k0);
            a1 = *(const float4*)(Ap1 + k0);
            cp_async16(&Bs[nxt][bkk    ][bcq << 2], Bp + (size_t)k0*N);
            cp_async16(&Bs[nxt][bkk + 8][bcq << 2], Bp + (size_t)(k0 + 8)*N);
            CP_COMMIT();
        }
        #pragma unroll
        for (int kk = 0; kk < 16; kk++) {
            float4 av0 = *(const float4*)&As[cur][kk][ty << 3];
            float4 av1 = *(const float4*)&As[cur][kk][(ty << 3) + 4];
            float4 bv0 = *(const float4*)&Bs[cur][kk][tx << 3];
            float4 bv1 = *(const float4*)&Bs[cur][kk][(tx << 3) + 4];
            float a_[8] = {av0.x, av0.y, av0.z, av0.w, av1.x, av1.y, av1.z, av1.w};
            float b_[8] = {bv0.x, bv0.y, bv0.z, bv0.w, bv1.x, bv1.y, bv1.z, bv1.w};
            #pragma unroll
            for (int i = 0; i < 8; i++)
                #pragma unroll
                for (int j = 0; j < 8; j++)
                    acc[i][j] = fmaf(a_[i], b_[j], acc[i][j]);
        }
        if (kt < T - 1) {
            As[nxt][(akq0<<2)+0][ar0] = a0.x;
            As[nxt][(akq0<<2)+1][ar0] = a0.y;
            As[nxt][(akq0<<2)+2][ar0] = a0.z;
            As[nxt][(akq0<<2)+3][ar0] = a0.w;
            As[nxt][(akq1<<2)+0][ar1] = a1.x;
            As[nxt][(akq1<<2)+1][ar1] = a1.y;
            As[nxt][(akq1<<2)+2][ar1] = a1.z;
            As[nxt][(akq1<<2)+3][ar1] = a1.w;
            CP_WAIT0();
            __syncthreads();
        }
    }

    #pragma unroll
    for (int i = 0; i < 8; i++) {
        int row = bm + (ty << 3) + i;
        float* crow = C + (size_t)row * N + bn + (tx << 3);
        if (EPI == 0) {
            float4 o0, o1;
            o0.x = acc[i][0]; o0.y = acc[i][1]; o0.z = acc[i][2]; o0.w = acc[i][3];
            o1.x = acc[i][4]; o1.y = acc[i][5]; o1.z = acc[i][6]; o1.w = acc[i][7];
            *(float4*)crow = o0;
            *(float4*)(crow + 4) = o1;
        } else {
            #pragma unroll
            for (int j = 0; j < 8; j++) {
                int col = bn + (tx << 3) + j;
                float val = acc[i][j];
                if (EPI == 2)      { float z = val + bias[col]; crow[j] = z > 0.f ? z : 0.01f*z; }
                else if (EPI == 3) crow[j] += val + bias[col];
                else if (EPI == 4) crow[j] += val;
            }
        }
    }
}

// ---------------- KV mean-pool into transposed [B,H,DH,NB] layout ----------------
__global__ void pool_kernel(const float* __restrict__ k, const float* __restrict__ v,
                            float* __restrict__ kc, float* __restrict__ vc)
{
    int wid = (blockIdx.x * blockDim.x + threadIdx.x) >> 5;  // [0, B*H*NB)
    int lane = threadIdx.x & 31;
    if (wid >= BB*HH*NB) return;
    int n = wid % NB;
    int h = (wid / NB) % HH;
    int b = wid / (NB*HH);
    float sk = 0.f, sv = 0.f;
    #pragma unroll
    for (int c = 0; c < 4; c++) {
        size_t idx = ((size_t)(b*SS + n*4 + c)*HH + h)*DHH + lane;
        sk += k[idx]; sv += v[idx];
    }
    size_t oidx = ((size_t)(b*HH + h)*DHH + lane)*NB + n;
    kc[oidx] = sk * 0.25f;
    vc[oidx] = sv * 0.25f;
}

// ---------------- fused NSA attention: one THREAD per (b,h,t), tiled kc/vc in smem ----------------
__global__ void __launch_bounds__(256) nsa_attn_kernel(
    const float* __restrict__ q, const float* __restrict__ k, const float* __restrict__ v,
    const float* __restrict__ kc, const float* __restrict__ vc,
    const float* __restrict__ g, float* __restrict__ o)
{
    __shared__ float kcs[32][64];
    __shared__ float vcs[32][64];

    int tid   = threadIdx.x;
    int qtile = blockIdx.x & (NQT - 1);
    int h     = (blockIdx.x / NQT) & (HH - 1);
    int b     = blockIdx.x / (NQT * HH);
    int t     = qtile * QT + tid;

    const float SCALE = 0.17677669529663687f;  // 32^-0.5
    float qv[32];
    {
        const float4* qr = (const float4*)(q + ((size_t)(b*SS + t)*HH + h)*DHH);
        #pragma unroll
        for (int i = 0; i < 8; i++) {
            float4 f = qr[i];
            qv[4*i+0] = f.x * SCALE; qv[4*i+1] = f.y * SCALE;
            qv[4*i+2] = f.z * SCALE; qv[4*i+3] = f.w * SCALE;
        }
    }

    int own = t >> 2;
    const float* kcb = kc + (size_t)(b*HH + h)*DHH*NB;
    const float* vcb = vc + (size_t)(b*HH + h)*DHH*NB;

    float Ml = -INFINITY, Z = 0.f;
    float av[32];
    #pragma unroll
    for (int j = 0; j < 32; j++) av[j] = 0.f;
    float bval = -INFINITY; int bidx = NB;

    for (int tile = 0; tile <= qtile; tile++) {
        int n0 = tile << 6;
        if (tile) __syncthreads();
        #pragma unroll
        for (int i = 0; i < 8; i++) {
            int idx = tid + (i << 8);
            int kk = idx >> 6, n = idx & 63;
            kcs[kk][n] = kcb[kk*NB + n0 + n];
            vcs[kk][n] = vcb[kk*NB + n0 + n];
        }
        __syncthreads();

        int lim = (tile == qtile) ? ((tid + 1) >> 2) : 64;

        for (int n4 = 0; n4 < 64; n4 += 4) {
            if (n4 >= lim) break;
            float s0 = 0.f, s1 = 0.f, s2 = 0.f, s3 = 0.f;
            #pragma unroll
            for (int kk = 0; kk < 32; kk++) {
                float4 kf = *(const float4*)&kcs[kk][n4];
                s0 = fmaf(qv[kk], kf.x, s0);
                s1 = fmaf(qv[kk], kf.y, s1);
                s2 = fmaf(qv[kk], kf.z, s2);
                s3 = fmaf(qv[kk], kf.w, s3);
            }
            if (n4 + 1 >= lim) s1 = -INFINITY;
            if (n4 + 2 >= lim) s2 = -INFINITY;
            if (n4 + 3 >= lim) s3 = -INFINITY;

            int gn = n0 + n4;
            if (gn + 0 != own && s0 > bval) { bval = s0; bidx = gn + 0; }
            if (gn + 1 != own && s1 > bval) { bval = s1; bidx = gn + 1; }
            if (gn + 2 != own && s2 > bval) { bval = s2; bidx = gn + 2; }
            if (gn + 3 != own && s3 > bval) { bval = s3; bidx = gn + 3; }

            float m4 = fmaxf(fmaxf(s0, s1), fmaxf(s2, s3));
            if (m4 > Ml) {
                float r = __expf(Ml - m4);
                Z *= r;
                #pragma unroll
                for (int j = 0; j < 32; j++) av[j] *= r;
                Ml = m4;
            }
            float p0 = __expf(s0 - Ml);
            float p1 = __expf(s1 - Ml);
            float p2 = __expf(s2 - Ml);
            float p3 = __expf(s3 - Ml);
            Z += (p0 + p1) + (p2 + p3);
            #pragma unroll
            for (int j = 0; j < 32; j++) {
                float4 vf = *(const float4*)&vcs[j][n4];
                av[j] = fmaf(p0, vf.x, av[j]);
                av[j] = fmaf(p1, vf.y, av[j]);
                av[j] = fmaf(p2, vf.z, av[j]);
                av[j] = fmaf(p3, vf.w, av[j]);
            }
        }
    }

    if (bval == -INFINITY) bidx = (own == 0) ? 1 : 0;

    const float* gr = g + (size_t)(b*SS + t)*24;
    float g0 = gr[h], g1 = gr[8 + h], g2 = gr[16 + h];

    float invZ = (Z > 0.f) ? (1.f / Z) : 0.f;
    float c0 = g0 * invZ;
    #pragma unroll
    for (int j = 0; j < 32; j++) av[j] *= c0;

    // ---- selection branch: blocks {own, bidx}, 8 keys, mask pos<=t ----
    float sc[8];
    float smax = -INFINITY;
    #pragma unroll
    for (int e = 0; e < 8; e++) {
        int pos = ((e < 4) ? own : bidx) * 4 + (e & 3);
        const float4* kr = (const float4*)(k + ((size_t)(b*SS + pos)*HH + h)*DHH);
        float s = 0.f;
        #pragma unroll
        for (int i = 0; i < 8; i++) {
            float4 kf = kr[i];
            s = fmaf(qv[4*i+0], kf.x, s);
            s = fmaf(qv[4*i+1], kf.y, s);
            s = fmaf(qv[4*i+2], kf.z, s);
            s = fmaf(qv[4*i+3], kf.w, s);
        }
        s = (pos <= t) ? s : -INFINITY;
        sc[e] = s;
        smax = fmaxf(smax, s);
    }
    float zf = 0.f;
    #pragma unroll
    for (int e = 0; e < 8; e++) { sc[e] = __expf(sc[e] - smax); zf += sc[e]; }
    float c1 = g1 / zf;
    #pragma unroll
    for (int e = 0; e < 8; e++) {
        int pos = ((e < 4) ? own : bidx) * 4 + (e & 3);
        float w = sc[e] * c1;
        const float4* vr = (const float4*)(v + ((size_t)(b*SS + pos)*HH + h)*DHH);
        #pragma unroll
        for (int i = 0; i < 8; i++) {
            float4 vf = vr[i];
            av[4*i+0] = fmaf(w, vf.x, av[4*i+0]);
            av[4*i+1] = fmaf(w, vf.y, av[4*i+1]);
            av[4*i+2] = fmaf(w, vf.z, av[4*i+2]);
            av[4*i+3] = fmaf(w, vf.w, av[4*i+3]);
        }
    }

    // ---- sliding-window branch: keys {t-1, t} ----
    int tp = (t > 0) ? t - 1 : 0;
    float s1w = 0.f, s0w = 0.f;
    {
        const float4* kr1 = (const float4*)(k + ((size_t)(b*SS + t )*HH + h)*DHH);
        const float4* kr0 = (const float4*)(k + ((size_t)(b*SS + tp)*HH + h)*DHH);
        #pragma unroll
        for (int i = 0; i < 8; i++) {
            float4 k1 = kr1[i], k0 = kr0[i];
            s1w = fmaf(qv[4*i+0], k1.x, s1w); s0w = fmaf(qv[4*i+0], k0.x, s0w);
            s1w = fmaf(qv[4*i+1], k1.y, s1w); s0w = fmaf(qv[4*i+1], k0.y, s0w);
            s1w = fmaf(qv[4*i+2], k1.z, s1w); s0w = fmaf(qv[4*i+2], k0.z, s0w);
            s1w = fmaf(qv[4*i+3], k1.w, s1w); s0w = fmaf(qv[4*i+3], k0.w, s0w);
        }
    }
    if (t == 0) s0w = -INFINITY;
    float wm = fmaxf(s0w, s1w);
    float p0w = __expf(s0w - wm), p1w = __expf(s1w - wm);
    float c2 = g2 / (p0w + p1w);
    float w0 = p0w * c2, w1 = p1w * c2;
    {
        const float4* vr1 = (const float4*)(v + ((size_t)(b*SS + t )*HH + h)*DHH);
        const float4* vr0 = (const float4*)(v + ((size_t)(b*SS + tp)*HH + h)*DHH);
        #pragma unroll
        for (int i = 0; i < 8; i++) {
            float4 v1 = vr1[i], v0 = vr0[i];
            av[4*i+0] = fmaf(w1, v1.x, fmaf(w0, v0.x, av[4*i+0]));
            av[4*i+1] = fmaf(w1, v1.y, fmaf(w0, v0.y, av[4*i+1]));
            av[4*i+2] = fmaf(w1, v1.z, fmaf(w0, v0.z, av[4*i+2]));
            av[4*i+3] = fmaf(w1, v1.w, fmaf(w0, v0.w, av[4*i+3]));
        }
    }

    float4* orow = (float4*)(o + ((size_t)(b*SS + t)*HH + h)*DHH);
    #pragma unroll
    for (int i = 0; i < 8; i++) {
        float4 f;
        f.x = av[4*i+0]; f.y = av[4*i+1]; f.z = av[4*i+2]; f.w = av[4*i+3];
        orow[i] = f;
    }
}

// ---------------- host orchestration ----------------
extern "C" void kernel_launch(void* const* d_in, const int* in_sizes, int n_in,
                              void* d_out, int out_size)
{
    const float* x_in   = (const float*)d_in[0];
    const float* ln_a_g = (const float*)d_in[1];
    const float* ln_a_b = (const float*)d_in[2];
    const float* Wq     = (const float*)d_in[3];
    const float* Wk     = (const float*)d_in[4];
    const float* Wv     = (const float*)d_in[5];
    const float* Wg     = (const float*)d_in[6];
    const float* Wo     = (const float*)d_in[7];
    const float* ln_f_g = (const float*)d_in[8];
    const float* ln_f_b = (const float*)d_in[9];
    const float* W1     = (const float*)d_in[10];
    const float* b1     = (const float*)d_in[11];
    const float* W2     = (const float*)d_in[12];
    const float* b2     = (const float*)d_in[13];
    float* x = (float*)d_out;

    float *ph, *pq, *pk, *pv, *po, *pg, *pkc, *pvc, *pmid;
    cudaGetSymbolAddress((void**)&ph,   g_h);
    cudaGetSymbolAddress((void**)&pq,   g_q);
    cudaGetSymbolAddress((void**)&pk,   g_k);
    cudaGetSymbolAddress((void**)&pv,   g_v);
    cudaGetSymbolAddress((void**)&po,   g_o);
    cudaGetSymbolAddress((void**)&pg,   g_g);
    cudaGetSymbolAddress((void**)&pkc,  g_kc);
    cudaGetSymbolAddress((void**)&pvc,  g_vc);
    cudaGetSymbolAddress((void**)&pmid, g_mid);

    cudaMemcpyAsync(x, x_in, (size_t)BSD * sizeof(float), cudaMemcpyDeviceToDevice, 0);

    for (int l = 0; l < 2; l++) {
        for (int j2 = 0; j2 < 2; j2++) {
            int li = l*2 + j2;
            ln_kernel<<<BS/8, 256>>>(x, ln_a_g + li*DIMM, ln_a_b + li*DIMM, ph);
            gemm128_kernel<0, true><<<dim3(2, 64, 3), 256>>>(
                ph,
                Wq + (size_t)li*DIMM*DIMM, Wk + (size_t)li*DIMM*DIMM, Wv + (size_t)li*DIMM*DIMM,
                nullptr, pq, pk, pv, BS, DIMM, DIMM);
            gate_gemm_kernel<<<dim3(1, BS/64), 256>>>(ph, Wg + (size_t)li*DIMM*24, pg, BS, 24, DIMM);
            pool_kernel<<<(BB*HH*NB*32)/256, 256>>>(pk, pv, pkc, pvc);
            nsa_attn_kernel<<<BB*HH*NQT, 256>>>(pq, pk, pv, pkc, pvc, pg, po);
            gemm128_kernel<4, false><<<dim3(2, 64), 256>>>(
                po, Wo + (size_t)li*DIMM*DIMM, nullptr, nullptr,
                nullptr, x, nullptr, nullptr, BS, DIMM, DIMM);
        }
        ln_kernel<<<BS/8, 256>>>(x, ln_f_g + l*DIMM, ln_f_b + l*DIMM, ph);
        gemm128_kernel<2, false><<<dim3(4, 64), 256>>>(
            ph, W1 + (size_t)l*DIMM*512, nullptr, nullptr,
            b1 + l*512, pmid, nullptr, nullptr, BS, 512, DIMM);
        gemm128_kernel<3, false><<<dim3(2, 64), 256>>>(
            pmid, W2 + (size_t)l*512*DIMM, nullptr, nullptr,
            b2 + l*DIMM, x, nullptr, nullptr, BS, DIMM, 512);
    }
}

// round 7
// speedup vs baseline: 1.3498x; 1.1356x over previous
#include <cuda_runtime.h>
#include <math.h>

#define BB   4
#define SS   2048
#define HH   8
#define DHH  32
#define DIMM 256
#define NB   512          // SS / 4 compressed blocks
#define BS   (BB*SS)      // 8192 rows
#define BSD  (BS*DIMM)    // 2097152 floats
#define QT   256          // queries per attn block
#define NQT  (SS/QT)      // 8 qtiles

// ---------------- scratch (static device buffers; no allocs) ----------------
__device__ float g_h  [BSD];
__device__ float g_q  [BSD];
__device__ float g_k  [BSD];
__device__ float g_v  [BSD];
__device__ float g_o  [BSD];
__device__ float g_g  [BS*24];
__device__ float g_kc [BB*HH*DHH*NB];
__device__ float g_vc [BB*HH*DHH*NB];
__device__ float g_mid[BS*512];

__device__ __forceinline__ unsigned f2tf32(float x) {
    unsigned u; asm("cvt.rna.tf32.f32 %0, %1;" : "=r"(u) : "f"(x)); return u;
}

__device__ __forceinline__ void mma_tf32(float* c, const unsigned* a, const unsigned* b) {
    asm volatile(
        "mma.sync.aligned.m16n8k8.row.col.f32.tf32.tf32.f32 "
        "{%0,%1,%2,%3}, {%4,%5,%6,%7}, {%8,%9}, {%0,%1,%2,%3};"
        : "+f"(c[0]), "+f"(c[1]), "+f"(c[2]), "+f"(c[3])
        : "r"(a[0]), "r"(a[1]), "r"(a[2]), "r"(a[3]), "r"(b[0]), "r"(b[1]));
}

// ---------------- LayerNorm: one warp per row of 256 ----------------
__global__ void ln_kernel(const float* __restrict__ x, const float* __restrict__ gw,
                          const float* __restrict__ bw, float* __restrict__ out)
{
    int warp = (blockIdx.x * blockDim.x + threadIdx.x) >> 5;
    int lane = threadIdx.x & 31;
    if (warp >= BS) return;
    const float* xr = x + (size_t)warp * DIMM;
    float vbuf[8];
    float s = 0.f;
    #pragma unroll
    for (int i = 0; i < 8; i++) { vbuf[i] = xr[lane + i*32]; s += vbuf[i]; }
    #pragma unroll
    for (int o = 16; o > 0; o >>= 1) s += __shfl_xor_sync(~0u, s, o);
    float m = s * (1.f/256.f);
    float sq = 0.f;
    #pragma unroll
    for (int i = 0; i < 8; i++) { float d = vbuf[i] - m; sq += d*d; }
    #pragma unroll
    for (int o = 16; o > 0; o >>= 1) sq += __shfl_xor_sync(~0u, sq, o);
    float rstd = rsqrtf(sq * (1.f/256.f) + 1e-5f);
    float* orow = out + (size_t)warp * DIMM;
    #pragma unroll
    for (int i = 0; i < 8; i++) {
        int c = lane + i*32;
        orow[c] = (vbuf[i] - m) * rstd * gw[c] + bw[c];
    }
}

// ---------------- small GEMM for gate (N=24), sigmoid epilogue ----------------
__global__ void __launch_bounds__(256) gate_gemm_kernel(
    const float* __restrict__ A, const float* __restrict__ B,
    float* __restrict__ C, int M, int N, int K)
{
    __shared__ float As[16][65];
    __shared__ float Bs[16][65];
    int tid = threadIdx.x;
    int tx = tid & 15, ty = tid >> 4;
    int bm = blockIdx.y << 6, bn = blockIdx.x << 6;
    float acc[4][4];
    #pragma unroll
    for (int i = 0; i < 4; i++)
        #pragma unroll
        for (int j = 0; j < 4; j++) acc[i][j] = 0.f;

    for (int k0 = 0; k0 < K; k0 += 16) {
        #pragma unroll
        for (int i = 0; i < 4; i++) {
            int e = tid + (i << 8);
            int r = e >> 4, kk = e & 15;
            As[kk][r] = A[(size_t)(bm + r)*K + k0 + kk];
        }
        #pragma unroll
        for (int i = 0; i < 4; i++) {
            int e = tid + (i << 8);
            int kk = e >> 6, c = e & 63;
            Bs[kk][c] = (bn + c < N) ? B[(size_t)(k0 + kk)*N + bn + c] : 0.f;
        }
        __syncthreads();
        #pragma unroll
        for (int kk = 0; kk < 16; kk++) {
            float a[4], bb[4];
            #pragma unroll
            for (int i = 0; i < 4; i++) a[i] = As[kk][(ty<<2)+i];
            #pragma unroll
            for (int j = 0; j < 4; j++) bb[j] = Bs[kk][(tx<<2)+j];
            #pragma unroll
            for (int i = 0; i < 4; i++)
                #pragma unroll
                for (int j = 0; j < 4; j++)
                    acc[i][j] = fmaf(a[i], bb[j], acc[i][j]);
        }
        __syncthreads();
    }
    #pragma unroll
    for (int i = 0; i < 4; i++) {
        int row = bm + (ty<<2) + i;
        #pragma unroll
        for (int j = 0; j < 4; j++) {
            int col = bn + (tx<<2) + j;
            if (col >= N) continue;
            C[(size_t)row * N + col] = 1.f / (1.f + expf(-acc[i][j]));
        }
    }
}

// ---------------- main GEMM: 3xTF32 tensor-core, 128x128 tile, BK=16 --------
// Error-compensated tf32: a = a_hi + a_lo, C += ah*bh + al*bh + ah*bl.
// 8 warps, warp tile 64x32, mma.m16n8k8. Requires M%128==0, N%128==0, K%16==0.
// EPI: 0=store  2=bias+leakyrelu  3=C+=val+bias  4=C+=val
// QKV=true: blockIdx.z in {0,1,2} selects (B0,C0)/(B1,C1)/(B2,C2)
#define AH_(b,r,c) sAh[((b)*128 + (r))*20 + (c)]
#define AL_(b,r,c) sAl[((b)*128 + (r))*20 + (c)]
#define BH_(b,k,c) sBh[((b)*16  + (k))*136 + (c)]
#define BL_(b,k,c) sBl[((b)*16  + (k))*136 + (c)]
#define GEMM_SMEM_BYTES ((2*128*20*2 + 2*16*136*2) * 4)

template<int EPI, bool QKV>
__global__ void __launch_bounds__(256, 2) mma_gemm_kernel(
    const float* __restrict__ A,
    const float* __restrict__ B0, const float* __restrict__ B1, const float* __restrict__ B2,
    const float* __restrict__ bias,
    float* __restrict__ C0, float* __restrict__ C1, float* __restrict__ C2,
    int M, int N, int K)
{
    extern __shared__ float sm_[];
    float* sAh = sm_;
    float* sAl = sAh + 2*128*20;
    float* sBh = sAl + 2*128*20;
    float* sBl = sBh + 2*16*136;

    const float* B = B0;
    float* C = C0;
    if (QKV) {
        if (blockIdx.z == 1)      { B = B1; C = C1; }
        else if (blockIdx.z == 2) { B = B2; C = C2; }
    }

    int tid  = threadIdx.x;
    int wid  = tid >> 5, lane = tid & 31;
    int g    = lane >> 2, tg = lane & 3;
    int wm   = (wid >> 2) << 6;   // 0 / 64
    int wn   = (wid & 3) << 5;    // 0 / 32 / 64 / 96
    int bm   = blockIdx.y << 7, bn = blockIdx.x << 7;

    int ar  = tid >> 2, akq = tid & 3;
    const float* Ap0 = A + (size_t)(bm + ar)*K + (akq << 2);
    const float* Ap1 = A + (size_t)(bm + 64 + ar)*K + (akq << 2);
    int bkk = tid >> 5, bcq = tid & 31;
    const float* Bp0 = B + (size_t)bkk*N + bn + (bcq << 2);
    const float* Bp1 = B + (size_t)(bkk + 8)*N + bn + (bcq << 2);

    float acc[4][4][4];
    #pragma unroll
    for (int mt = 0; mt < 4; mt++)
        #pragma unroll
        for (int nt = 0; nt < 4; nt++)
            #pragma unroll
            for (int r = 0; r < 4; r++) acc[mt][nt][r] = 0.f;

    // ---- prologue: tile 0 -> buffer 0 ----
    {
        float4 a0 = *(const float4*)Ap0;
        float4 a1 = *(const float4*)Ap1;
        float4 b0 = *(const float4*)Bp0;
        float4 b1 = *(const float4*)Bp1;
        float av0[4] = {a0.x, a0.y, a0.z, a0.w};
        float av1[4] = {a1.x, a1.y, a1.z, a1.w};
        #pragma unroll
        for (int e = 0; e < 4; e++) {
            float h0 = __uint_as_float(f2tf32(av0[e]));
            float h1 = __uint_as_float(f2tf32(av1[e]));
            AH_(0, ar,      (akq<<2)+e) = h0;
            AL_(0, ar,      (akq<<2)+e) = __uint_as_float(f2tf32(av0[e] - h0));
            AH_(0, ar + 64, (akq<<2)+e) = h1;
            AL_(0, ar + 64, (akq<<2)+e) = __uint_as_float(f2tf32(av1[e] - h1));
        }
        float4 h, l;
        h.x = __uint_as_float(f2tf32(b0.x)); l.x = __uint_as_float(f2tf32(b0.x - h.x));
        h.y = __uint_as_float(f2tf32(b0.y)); l.y = __uint_as_float(f2tf32(b0.y - h.y));
        h.z = __uint_as_float(f2tf32(b0.z)); l.z = __uint_as_float(f2tf32(b0.z - h.z));
        h.w = __uint_as_float(f2tf32(b0.w)); l.w = __uint_as_float(f2tf32(b0.w - h.w));
        *(float4*)&BH_(0, bkk, bcq<<2) = h;
        *(float4*)&BL_(0, bkk, bcq<<2) = l;
        h.x = __uint_as_float(f2tf32(b1.x)); l.x = __uint_as_float(f2tf32(b1.x - h.x));
        h.y = __uint_as_float(f2tf32(b1.y)); l.y = __uint_as_float(f2tf32(b1.y - h.y));
        h.z = __uint_as_float(f2tf32(b1.z)); l.z = __uint_as_float(f2tf32(b1.z - h.z));
        h.w = __uint_as_float(f2tf32(b1.w)); l.w = __uint_as_float(f2tf32(b1.w - h.w));
        *(float4*)&BH_(0, bkk + 8, bcq<<2) = h;
        *(float4*)&BL_(0, bkk + 8, bcq<<2) = l;
        __syncthreads();
    }

    int T = K >> 4;
    for (int kt = 0; kt < T; kt++) {
        int cur = kt & 1, nxt = cur ^ 1;
        float4 a0, a1, b0, b1;
        if (kt < T - 1) {
            int k0 = (kt + 1) << 4;
            a0 = *(const float4*)(Ap0 + k0);
            a1 = *(const float4*)(Ap1 + k0);
            b0 = *(const float4*)(Bp0 + (size_t)k0*N);
            b1 = *(const float4*)(Bp1 + (size_t)k0*N);
        }
        #pragma unroll
        for (int k8 = 0; k8 < 16; k8 += 8) {
            unsigned bh[4][2], bl[4][2];
            #pragma unroll
            for (int nt = 0; nt < 4; nt++) {
                int c = wn + (nt << 3) + g;
                bh[nt][0] = __float_as_uint(BH_(cur, k8 + tg,     c));
                bh[nt][1] = __float_as_uint(BH_(cur, k8 + tg + 4, c));
                bl[nt][0] = __float_as_uint(BL_(cur, k8 + tg,     c));
                bl[nt][1] = __float_as_uint(BL_(cur, k8 + tg + 4, c));
            }
            #pragma unroll
            for (int mt = 0; mt < 4; mt++) {
                int r = wm + (mt << 4) + g;
                unsigned ah[4], al[4];
                ah[0] = __float_as_uint(AH_(cur, r,     k8 + tg));
                ah[1] = __float_as_uint(AH_(cur, r + 8, k8 + tg));
                ah[2] = __float_as_uint(AH_(cur, r,     k8 + tg + 4));
                ah[3] = __float_as_uint(AH_(cur, r + 8, k8 + tg + 4));
                al[0] = __float_as_uint(AL_(cur, r,     k8 + tg));
                al[1] = __float_as_uint(AL_(cur, r + 8, k8 + tg));
                al[2] = __float_as_uint(AL_(cur, r,     k8 + tg + 4));
                al[3] = __float_as_uint(AL_(cur, r + 8, k8 + tg + 4));
                #pragma unroll
                for (int nt = 0; nt < 4; nt++) {
                    mma_tf32(acc[mt][nt], ah, bh[nt]);
                    mma_tf32(acc[mt][nt], al, bh[nt]);
                    mma_tf32(acc[mt][nt], ah, bl[nt]);
                }
            }
        }
        if (kt < T - 1) {
            float av0[4] = {a0.x, a0.y, a0.z, a0.w};
            float av1[4] = {a1.x, a1.y, a1.z, a1.w};
            #pragma unroll
            for (int e = 0; e < 4; e++) {
                float h0 = __uint_as_float(f2tf32(av0[e]));
                float h1 = __uint_as_float(f2tf32(av1[e]));
                AH_(nxt, ar,      (akq<<2)+e) = h0;
                AL_(nxt, ar,      (akq<<2)+e) = __uint_as_float(f2tf32(av0[e] - h0));
                AH_(nxt, ar + 64, (akq<<2)+e) = h1;
                AL_(nxt, ar + 64, (akq<<2)+e) = __uint_as_float(f2tf32(av1[e] - h1));
            }
            float4 h, l;
            h.x = __uint_as_float(f2tf32(b0.x)); l.x = __uint_as_float(f2tf32(b0.x - h.x));
            h.y = __uint_as_float(f2tf32(b0.y)); l.y = __uint_as_float(f2tf32(b0.y - h.y));
            h.z = __uint_as_float(f2tf32(b0.z)); l.z = __uint_as_float(f2tf32(b0.z - h.z));
            h.w = __uint_as_float(f2tf32(b0.w)); l.w = __uint_as_float(f2tf32(b0.w - h.w));
            *(float4*)&BH_(nxt, bkk, bcq<<2) = h;
            *(float4*)&BL_(nxt, bkk, bcq<<2) = l;
            h.x = __uint_as_float(f2tf32(b1.x)); l.x = __uint_as_float(f2tf32(b1.x - h.x));
            h.y = __uint_as_float(f2tf32(b1.y)); l.y = __uint_as_float(f2tf32(b1.y - h.y));
            h.z = __uint_as_float(f2tf32(b1.z)); l.z = __uint_as_float(f2tf32(b1.z - h.z));
            h.w = __uint_as_float(f2tf32(b1.w)); l.w = __uint_as_float(f2tf32(b1.w - h.w));
            *(float4*)&BH_(nxt, bkk + 8, bcq<<2) = h;
            *(float4*)&BL_(nxt, bkk + 8, bcq<<2) = l;
            __syncthreads();
        }
    }

    // ---- epilogue ----
    #pragma unroll
    for (int mt = 0; mt < 4; mt++) {
        #pragma unroll
        for (int nt = 0; nt < 4; nt++) {
            int r0 = bm + wm + (mt << 4) + g;
            int cc = bn + wn + (nt << 3) + (tg << 1);
            float* p0 = C + (size_t)r0 * N + cc;
            float* p1 = C + (size_t)(r0 + 8) * N + cc;
            float v00 = acc[mt][nt][0], v01 = acc[mt][nt][1];
            float v10 = acc[mt][nt][2], v11 = acc[mt][nt][3];
            if (EPI == 0) {
                *(float2*)p0 = make_float2(v00, v01);
                *(float2*)p1 = make_float2(v10, v11);
            } else if (EPI == 2) {
                float b0v = bias[cc], b1v = bias[cc + 1];
                float z;
                z = v00 + b0v; v00 = z > 0.f ? z : 0.01f*z;
                z = v01 + b1v; v01 = z > 0.f ? z : 0.01f*z;
                z = v10 + b0v; v10 = z > 0.f ? z : 0.01f*z;
                z = v11 + b1v; v11 = z > 0.f ? z : 0.01f*z;
                *(float2*)p0 = make_float2(v00, v01);
                *(float2*)p1 = make_float2(v10, v11);
            } else if (EPI == 3) {
                float b0v = bias[cc], b1v = bias[cc + 1];
                float2 o0 = *(float2*)p0, o1 = *(float2*)p1;
                o0.x += v00 + b0v; o0.y += v01 + b1v;
                o1.x += v10 + b0v; o1.y += v11 + b1v;
                *(float2*)p0 = o0;
                *(float2*)p1 = o1;
            } else if (EPI == 4) {
                float2 o0 = *(float2*)p0, o1 = *(float2*)p1;
                o0.x += v00; o0.y += v01;
                o1.x += v10; o1.y += v11;
                *(float2*)p0 = o0;
                *(float2*)p1 = o1;
            }
        }
    }
}

// ---------------- KV mean-pool into transposed [B,H,DH,NB] layout ----------------
__global__ void pool_kernel(const float* __restrict__ k, const float* __restrict__ v,
                            float* __restrict__ kc, float* __restrict__ vc)
{
    int wid = (blockIdx.x * blockDim.x + threadIdx.x) >> 5;  // [0, B*H*NB)
    int lane = threadIdx.x & 31;
    if (wid >= BB*HH*NB) return;
    int n = wid % NB;
    int h = (wid / NB) % HH;
    int b = wid / (NB*HH);
    float sk = 0.f, sv = 0.f;
    #pragma unroll
    for (int c = 0; c < 4; c++) {
        size_t idx = ((size_t)(b*SS + n*4 + c)*HH + h)*DHH + lane;
        sk += k[idx]; sv += v[idx];
    }
    size_t oidx = ((size_t)(b*HH + h)*DHH + lane)*NB + n;
    kc[oidx] = sk * 0.25f;
    vc[oidx] = sv * 0.25f;
}

// ---------------- fused NSA attention: one THREAD per (b,h,t), tiled kc/vc in smem ----------------
__global__ void __launch_bounds__(256) nsa_attn_kernel(
    const float* __restrict__ q, const float* __restrict__ k, const float* __restrict__ v,
    const float* __restrict__ kc, const float* __restrict__ vc,
    const float* __restrict__ g, float* __restrict__ o)
{
    __shared__ float kcs[32][64];
    __shared__ float vcs[32][64];

    int tid   = threadIdx.x;
    // heavy qtiles first: reduces tail imbalance across waves
    int qtile = (NQT - 1) - (blockIdx.x & (NQT - 1));
    int h     = (blockIdx.x / NQT) & (HH - 1);
    int b     = blockIdx.x / (NQT * HH);
    int t     = qtile * QT + tid;

    const float SCALE = 0.17677669529663687f;  // 32^-0.5
    float qv[32];
    {
        const float4* qr = (const float4*)(q + ((size_t)(b*SS + t)*HH + h)*DHH);
        #pragma unroll
        for (int i = 0; i < 8; i++) {
            float4 f = qr[i];
            qv[4*i+0] = f.x * SCALE; qv[4*i+1] = f.y * SCALE;
            qv[4*i+2] = f.z * SCALE; qv[4*i+3] = f.w * SCALE;
        }
    }

    int own = t >> 2;
    const float* kcb = kc + (size_t)(b*HH + h)*DHH*NB;
    const float* vcb = vc + (size_t)(b*HH + h)*DHH*NB;

    float Ml = -INFINITY, Z = 0.f;
    float av[32];
    #pragma unroll
    for (int j = 0; j < 32; j++) av[j] = 0.f;
    float bval = -INFINITY; int bidx = NB;

    for (int tile = 0; tile <= qtile; tile++) {
        int n0 = tile << 6;
        if (tile) __syncthreads();
        #pragma unroll
        for (int i = 0; i < 8; i++) {
            int idx = tid + (i << 8);
            int kk = idx >> 6, n = idx & 63;
            kcs[kk][n] = kcb[kk*NB + n0 + n];
            vcs[kk][n] = vcb[kk*NB + n0 + n];
        }
        __syncthreads();

        int lim = (tile == qtile) ? ((tid + 1) >> 2) : 64;

        for (int n4 = 0; n4 < 64; n4 += 4) {
            if (n4 >= lim) break;
            float s0 = 0.f, s1 = 0.f, s2 = 0.f, s3 = 0.f;
            #pragma unroll
            for (int kk = 0; kk < 32; kk++) {
                float4 kf = *(const float4*)&kcs[kk][n4];
                s0 = fmaf(qv[kk], kf.x, s0);
                s1 = fmaf(qv[kk], kf.y, s1);
                s2 = fmaf(qv[kk], kf.z, s2);
                s3 = fmaf(qv[kk], kf.w, s3);
            }
            if (n4 + 1 >= lim) s1 = -INFINITY;
            if (n4 + 2 >= lim) s2 = -INFINITY;
            if (n4 + 3 >= lim) s3 = -INFINITY;

            int gn = n0 + n4;
            if (gn + 0 != own && s0 > bval) { bval = s0; bidx = gn + 0; }
            if (gn + 1 != own && s1 > bval) { bval = s1; bidx = gn + 1; }
            if (gn + 2 != own && s2 > bval) { bval = s2; bidx = gn + 2; }
            if (gn + 3 != own && s3 > bval) { bval = s3; bidx = gn + 3; }

            float m4 = fmaxf(fmaxf(s0, s1), fmaxf(s2, s3));
            if (m4 > Ml) {
                float r = __expf(Ml - m4);
                Z *= r;
                #pragma unroll
                for (int j = 0; j < 32; j++) av[j] *= r;
                Ml = m4;
            }
            float p0 = __expf(s0 - Ml);
            float p1 = __expf(s1 - Ml);
            float p2 = __expf(s2 - Ml);
            float p3 = __expf(s3 - Ml);
            Z += (p0 + p1) + (p2 + p3);
            #pragma unroll
            for (int j = 0; j < 32; j++) {
                float4 vf = *(const float4*)&vcs[j][n4];
                av[j] = fmaf(p0, vf.x, av[j]);
                av[j] = fmaf(p1, vf.y, av[j]);
                av[j] = fmaf(p2, vf.z, av[j]);
                av[j] = fmaf(p3, vf.w, av[j]);
            }
        }
    }

    if (bval == -INFINITY) bidx = (own == 0) ? 1 : 0;

    const float* gr = g + (size_t)(b*SS + t)*24;
    float g0 = gr[h], g1 = gr[8 + h], g2 = gr[16 + h];

    float invZ = (Z > 0.f) ? (1.f / Z) : 0.f;
    float c0 = g0 * invZ;
    #pragma unroll
    for (int j = 0; j < 32; j++) av[j] *= c0;

    // ---- selection branch: blocks {own, bidx}, 8 keys, mask pos<=t ----
    float sc[8];
    float smax = -INFINITY;
    #pragma unroll
    for (int e = 0; e < 8; e++) {
        int pos = ((e < 4) ? own : bidx) * 4 + (e & 3);
        const float4* kr = (const float4*)(k + ((size_t)(b*SS + pos)*HH + h)*DHH);
        float s = 0.f;
        #pragma unroll
        for (int i = 0; i < 8; i++) {
            float4 kf = kr[i];
            s = fmaf(qv[4*i+0], kf.x, s);
            s = fmaf(qv[4*i+1], kf.y, s);
            s = fmaf(qv[4*i+2], kf.z, s);
            s = fmaf(qv[4*i+3], kf.w, s);
        }
        s = (pos <= t) ? s : -INFINITY;
        sc[e] = s;
        smax = fmaxf(smax, s);
    }
    float zf = 0.f;
    #pragma unroll
    for (int e = 0; e < 8; e++) { sc[e] = __expf(sc[e] - smax); zf += sc[e]; }
    float c1 = g1 / zf;
    #pragma unroll
    for (int e = 0; e < 8; e++) {
        int pos = ((e < 4) ? own : bidx) * 4 + (e & 3);
        float w = sc[e] * c1;
        const float4* vr = (const float4*)(v + ((size_t)(b*SS + pos)*HH + h)*DHH);
        #pragma unroll
        for (int i = 0; i < 8; i++) {
            float4 vf = vr[i];
            av[4*i+0] = fmaf(w, vf.x, av[4*i+0]);
            av[4*i+1] = fmaf(w, vf.y, av[4*i+1]);
            av[4*i+2] = fmaf(w, vf.z, av[4*i+2]);
            av[4*i+3] = fmaf(w, vf.w, av[4*i+3]);
        }
    }

    // ---- sliding-window branch: keys {t-1, t} ----
    int tp = (t > 0) ? t - 1 : 0;
    float s1w = 0.f, s0w = 0.f;
    {
        const float4* kr1 = (const float4*)(k + ((size_t)(b*SS + t )*HH + h)*DHH);
        const float4* kr0 = (const float4*)(k + ((size_t)(b*SS + tp)*HH + h)*DHH);
        #pragma unroll
        for (int i = 0; i < 8; i++) {
            float4 k1 = kr1[i], k0 = kr0[i];
            s1w = fmaf(qv[4*i+0], k1.x, s1w); s0w = fmaf(qv[4*i+0], k0.x, s0w);
            s1w = fmaf(qv[4*i+1], k1.y, s1w); s0w = fmaf(qv[4*i+1], k0.y, s0w);
            s1w = fmaf(qv[4*i+2], k1.z, s1w); s0w = fmaf(qv[4*i+2], k0.z, s0w);
            s1w = fmaf(qv[4*i+3], k1.w, s1w); s0w = fmaf(qv[4*i+3], k0.w, s0w);
        }
    }
    if (t == 0) s0w = -INFINITY;
    float wm = fmaxf(s0w, s1w);
    float p0w = __expf(s0w - wm), p1w = __expf(s1w - wm);
    float c2 = g2 / (p0w + p1w);
    float w0 = p0w * c2, w1 = p1w * c2;
    {
        const float4* vr1 = (const float4*)(v + ((size_t)(b*SS + t )*HH + h)*DHH);
        const float4* vr0 = (const float4*)(v + ((size_t)(b*SS + tp)*HH + h)*DHH);
        #pragma unroll
        for (int i = 0; i < 8; i++) {
            float4 v1 = vr1[i], v0 = vr0[i];
            av[4*i+0] = fmaf(w1, v1.x, fmaf(w0, v0.x, av[4*i+0]));
            av[4*i+1] = fmaf(w1, v1.y, fmaf(w0, v0.y, av[4*i+1]));
            av[4*i+2] = fmaf(w1, v1.z, fmaf(w0, v0.z, av[4*i+2]));
            av[4*i+3] = fmaf(w1, v1.w, fmaf(w0, v0.w, av[4*i+3]));
        }
    }

    float4* orow = (float4*)(o + ((size_t)(b*SS + t)*HH + h)*DHH);
    #pragma unroll
    for (int i = 0; i < 8; i++) {
        float4 f;
        f.x = av[4*i+0]; f.y = av[4*i+1]; f.z = av[4*i+2]; f.w = av[4*i+3];
        orow[i] = f;
    }
}

// ---------------- host orchestration ----------------
extern "C" void kernel_launch(void* const* d_in, const int* in_sizes, int n_in,
                              void* d_out, int out_size)
{
    const float* x_in   = (const float*)d_in[0];
    const float* ln_a_g = (const float*)d_in[1];
    const float* ln_a_b = (const float*)d_in[2];
    const float* Wq     = (const float*)d_in[3];
    const float* Wk     = (const float*)d_in[4];
    const float* Wv     = (const float*)d_in[5];
    const float* Wg     = (const float*)d_in[6];
    const float* Wo     = (const float*)d_in[7];
    const float* ln_f_g = (const float*)d_in[8];
    const float* ln_f_b = (const float*)d_in[9];
    const float* W1     = (const float*)d_in[10];
    const float* b1     = (const float*)d_in[11];
    const float* W2     = (const float*)d_in[12];
    const float* b2     = (const float*)d_in[13];
    float* x = (float*)d_out;

    float *ph, *pq, *pk, *pv, *po, *pg, *pkc, *pvc, *pmid;
    cudaGetSymbolAddress((void**)&ph,   g_h);
    cudaGetSymbolAddress((void**)&pq,   g_q);
    cudaGetSymbolAddress((void**)&pk,   g_k);
    cudaGetSymbolAddress((void**)&pv,   g_v);
    cudaGetSymbolAddress((void**)&po,   g_o);
    cudaGetSymbolAddress((void**)&pg,   g_g);
    cudaGetSymbolAddress((void**)&pkc,  g_kc);
    cudaGetSymbolAddress((void**)&pvc,  g_vc);
    cudaGetSymbolAddress((void**)&pmid, g_mid);

    // raise dynamic smem limits (host-side attribute set; not a stream op)
    cudaFuncSetAttribute(mma_gemm_kernel<0, true>,  cudaFuncAttributeMaxDynamicSharedMemorySize, GEMM_SMEM_BYTES);
    cudaFuncSetAttribute(mma_gemm_kernel<4, false>, cudaFuncAttributeMaxDynamicSharedMemorySize, GEMM_SMEM_BYTES);
    cudaFuncSetAttribute(mma_gemm_kernel<2, false>, cudaFuncAttributeMaxDynamicSharedMemorySize, GEMM_SMEM_BYTES);
    cudaFuncSetAttribute(mma_gemm_kernel<3, false>, cudaFuncAttributeMaxDynamicSharedMemorySize, GEMM_SMEM_BYTES);

    cudaMemcpyAsync(x, x_in, (size_t)BSD * sizeof(float), cudaMemcpyDeviceToDevice, 0);

    for (int l = 0; l < 2; l++) {
        for (int j2 = 0; j2 < 2; j2++) {
            int li = l*2 + j2;
            ln_kernel<<<BS/8, 256>>>(x, ln_a_g + li*DIMM, ln_a_b + li*DIMM, ph);
            mma_gemm_kernel<0, true><<<dim3(2, 64, 3), 256, GEMM_SMEM_BYTES>>>(
                ph,
                Wq + (size_t)li*DIMM*DIMM, Wk + (size_t)li*DIMM*DIMM, Wv + (size_t)li*DIMM*DIMM,
                nullptr, pq, pk, pv, BS, DIMM, DIMM);
            gate_gemm_kernel<<<dim3(1, BS/64), 256>>>(ph, Wg + (size_t)li*DIMM*24, pg, BS, 24, DIMM);
            pool_kernel<<<(BB*HH*NB*32)/256, 256>>>(pk, pv, pkc, pvc);
            nsa_attn_kernel<<<BB*HH*NQT, 256>>>(pq, pk, pv, pkc, pvc, pg, po);
            mma_gemm_kernel<4, false><<<dim3(2, 64), 256, GEMM_SMEM_BYTES>>>(
                po, Wo + (size_t)li*DIMM*DIMM, nullptr, nullptr,
                nullptr, x, nullptr, nullptr, BS, DIMM, DIMM);
        }
        ln_kernel<<<BS/8, 256>>>(x, ln_f_g + l*DIMM, ln_f_b + l*DIMM, ph);
        mma_gemm_kernel<2, false><<<dim3(4, 64), 256, GEMM_SMEM_BYTES>>>(
            ph, W1 + (size_t)l*DIMM*512, nullptr, nullptr,
            b1 + l*512, pmid, nullptr, nullptr, BS, 512, DIMM);
        mma_gemm_kernel<3, false><<<dim3(2, 64), 256, GEMM_SMEM_BYTES>>>(
            pmid, W2 + (size_t)l*512*DIMM, nullptr, nullptr,
            b2 + l*DIMM, x, nullptr, nullptr, BS, DIMM, 512);
    }
}

// round 8
// speedup vs baseline: 1.4329x; 1.0616x over previous
#include <cuda_runtime.h>
#include <math.h>

#define BB   4
#define SS   2048
#define HH   8
#define DHH  32
#define DIMM 256
#define NB   512          // SS / 4 compressed blocks
#define BS   (BB*SS)      // 8192 rows
#define BSD  (BS*DIMM)    // 2097152 floats
#define QT   256          // queries per attn block
#define NQT  (SS/QT)      // 8 qtiles

typedef unsigned long long ull;

// ---------------- scratch (static device buffers; no allocs) ----------------
__device__ float g_h  [BSD];
__device__ float g_q  [BSD];
__device__ float g_k  [BSD];
__device__ float g_v  [BSD];
__device__ float g_o  [BSD];
__device__ float g_g  [BS*24];
__device__ float g_kc [BB*HH*NB*DHH];
__device__ float g_vc [BB*HH*NB*DHH];
__device__ float g_mid[BS*512];

__device__ __forceinline__ unsigned f2tf32(float x) {
    unsigned u; asm("cvt.rna.tf32.f32 %0, %1;" : "=r"(u) : "f"(x)); return u;
}

__device__ __forceinline__ void mma_tf32(float* c, const unsigned* a, const unsigned* b) {
    asm volatile(
        "mma.sync.aligned.m16n8k8.row.col.f32.tf32.tf32.f32 "
        "{%0,%1,%2,%3}, {%4,%5,%6,%7}, {%8,%9}, {%0,%1,%2,%3};"
        : "+f"(c[0]), "+f"(c[1]), "+f"(c[2]), "+f"(c[3])
        : "r"(a[0]), "r"(a[1]), "r"(a[2]), "r"(a[3]), "r"(b[0]), "r"(b[1]));
}

// ---------------- packed f32x2 helpers (sm_100a) ----------------
__device__ __forceinline__ ull pk2(float lo, float hi) {
    ull r; asm("mov.b64 %0, {%1,%2};" : "=l"(r) : "f"(lo), "f"(hi)); return r;
}
__device__ __forceinline__ void upk2(float& lo, float& hi, ull v) {
    asm("mov.b64 {%0,%1}, %2;" : "=f"(lo), "=f"(hi) : "l"(v));
}
__device__ __forceinline__ ull fma2(ull a, ull b, ull c) {
    ull d; asm("fma.rn.f32x2 %0, %1, %2, %3;" : "=l"(d) : "l"(a), "l"(b), "l"(c)); return d;
}
__device__ __forceinline__ ull mul2(ull a, ull b) {
    ull d; asm("mul.rn.f32x2 %0, %1, %2;" : "=l"(d) : "l"(a), "l"(b)); return d;
}

// ---------------- LayerNorm: one warp per row of 256 ----------------
__global__ void ln_kernel(const float* __restrict__ x, const float* __restrict__ gw,
                          const float* __restrict__ bw, float* __restrict__ out)
{
    int warp = (blockIdx.x * blockDim.x + threadIdx.x) >> 5;
    int lane = threadIdx.x & 31;
    if (warp >= BS) return;
    const float* xr = x + (size_t)warp * DIMM;
    float vbuf[8];
    float s = 0.f;
    #pragma unroll
    for (int i = 0; i < 8; i++) { vbuf[i] = xr[lane + i*32]; s += vbuf[i]; }
    #pragma unroll
    for (int o = 16; o > 0; o >>= 1) s += __shfl_xor_sync(~0u, s, o);
    float m = s * (1.f/256.f);
    float sq = 0.f;
    #pragma unroll
    for (int i = 0; i < 8; i++) { float d = vbuf[i] - m; sq += d*d; }
    #pragma unroll
    for (int o = 16; o > 0; o >>= 1) sq += __shfl_xor_sync(~0u, sq, o);
    float rstd = rsqrtf(sq * (1.f/256.f) + 1e-5f);
    float* orow = out + (size_t)warp * DIMM;
    #pragma unroll
    for (int i = 0; i < 8; i++) {
        int c = lane + i*32;
        orow[c] = (vbuf[i] - m) * rstd * gw[c] + bw[c];
    }
}

// ---------------- small GEMM for gate (N=24), sigmoid epilogue ----------------
__global__ void __launch_bounds__(256) gate_gemm_kernel(
    const float* __restrict__ A, const float* __restrict__ B,
    float* __restrict__ C, int M, int N, int K)
{
    __shared__ float As[16][65];
    __shared__ float Bs[16][65];
    int tid = threadIdx.x;
    int tx = tid & 15, ty = tid >> 4;
    int bm = blockIdx.y << 6, bn = blockIdx.x << 6;
    float acc[4][4];
    #pragma unroll
    for (int i = 0; i < 4; i++)
        #pragma unroll
        for (int j = 0; j < 4; j++) acc[i][j] = 0.f;

    for (int k0 = 0; k0 < K; k0 += 16) {
        #pragma unroll
        for (int i = 0; i < 4; i++) {
            int e = tid + (i << 8);
            int r = e >> 4, kk = e & 15;
            As[kk][r] = A[(size_t)(bm + r)*K + k0 + kk];
        }
        #pragma unroll
        for (int i = 0; i < 4; i++) {
            int e = tid + (i << 8);
            int kk = e >> 6, c = e & 63;
            Bs[kk][c] = (bn + c < N) ? B[(size_t)(k0 + kk)*N + bn + c] : 0.f;
        }
        __syncthreads();
        #pragma unroll
        for (int kk = 0; kk < 16; kk++) {
            float a[4], bb[4];
            #pragma unroll
            for (int i = 0; i < 4; i++) a[i] = As[kk][(ty<<2)+i];
            #pragma unroll
            for (int j = 0; j < 4; j++) bb[j] = Bs[kk][(tx<<2)+j];
            #pragma unroll
            for (int i = 0; i < 4; i++)
                #pragma unroll
                for (int j = 0; j < 4; j++)
                    acc[i][j] = fmaf(a[i], bb[j], acc[i][j]);
        }
        __syncthreads();
    }
    #pragma unroll
    for (int i = 0; i < 4; i++) {
        int row = bm + (ty<<2) + i;
        #pragma unroll
        for (int j = 0; j < 4; j++) {
            int col = bn + (tx<<2) + j;
            if (col >= N) continue;
            C[(size_t)row * N + col] = 1.f / (1.f + expf(-acc[i][j]));
        }
    }
}

// ---------------- main GEMM: 3xTF32 tensor-core, 128x128 tile, BK=16 --------
#define AH_(b,r,c) sAh[((b)*128 + (r))*20 + (c)]
#define AL_(b,r,c) sAl[((b)*128 + (r))*20 + (c)]
#define BH_(b,k,c) sBh[((b)*16  + (k))*136 + (c)]
#define BL_(b,k,c) sBl[((b)*16  + (k))*136 + (c)]
#define GEMM_SMEM_BYTES ((2*128*20*2 + 2*16*136*2) * 4)

template<int EPI, bool QKV>
__global__ void __launch_bounds__(256, 2) mma_gemm_kernel(
    const float* __restrict__ A,
    const float* __restrict__ B0, const float* __restrict__ B1, const float* __restrict__ B2,
    const float* __restrict__ bias,
    float* __restrict__ C0, float* __restrict__ C1, float* __restrict__ C2,
    int M, int N, int K)
{
    extern __shared__ float sm_[];
    float* sAh = sm_;
    float* sAl = sAh + 2*128*20;
    float* sBh = sAl + 2*128*20;
    float* sBl = sBh + 2*16*136;

    const float* B = B0;
    float* C = C0;
    if (QKV) {
        if (blockIdx.z == 1)      { B = B1; C = C1; }
        else if (blockIdx.z == 2) { B = B2; C = C2; }
    }

    int tid  = threadIdx.x;
    int wid  = tid >> 5, lane = tid & 31;
    int g    = lane >> 2, tg = lane & 3;
    int wm   = (wid >> 2) << 6;
    int wn   = (wid & 3) << 5;
    int bm   = blockIdx.y << 7, bn = blockIdx.x << 7;

    int ar  = tid >> 2, akq = tid & 3;
    const float* Ap0 = A + (size_t)(bm + ar)*K + (akq << 2);
    const float* Ap1 = A + (size_t)(bm + 64 + ar)*K + (akq << 2);
    int bkk = tid >> 5, bcq = tid & 31;
    const float* Bp0 = B + (size_t)bkk*N + bn + (bcq << 2);
    const float* Bp1 = B + (size_t)(bkk + 8)*N + bn + (bcq << 2);

    float acc[4][4][4];
    #pragma unroll
    for (int mt = 0; mt < 4; mt++)
        #pragma unroll
        for (int nt = 0; nt < 4; nt++)
            #pragma unroll
            for (int r = 0; r < 4; r++) acc[mt][nt][r] = 0.f;

    // ---- prologue: tile 0 -> buffer 0 ----
    {
        float4 a0 = *(const float4*)Ap0;
        float4 a1 = *(const float4*)Ap1;
        float4 b0 = *(const float4*)Bp0;
        float4 b1 = *(const float4*)Bp1;
        float av0[4] = {a0.x, a0.y, a0.z, a0.w};
        float av1[4] = {a1.x, a1.y, a1.z, a1.w};
        #pragma unroll
        for (int e = 0; e < 4; e++) {
            float h0 = __uint_as_float(f2tf32(av0[e]));
            float h1 = __uint_as_float(f2tf32(av1[e]));
            AH_(0, ar,      (akq<<2)+e) = h0;
            AL_(0, ar,      (akq<<2)+e) = __uint_as_float(f2tf32(av0[e] - h0));
            AH_(0, ar + 64, (akq<<2)+e) = h1;
            AL_(0, ar + 64, (akq<<2)+e) = __uint_as_float(f2tf32(av1[e] - h1));
        }
        float4 h, l;
        h.x = __uint_as_float(f2tf32(b0.x)); l.x = __uint_as_float(f2tf32(b0.x - h.x));
        h.y = __uint_as_float(f2tf32(b0.y)); l.y = __uint_as_float(f2tf32(b0.y - h.y));
        h.z = __uint_as_float(f2tf32(b0.z)); l.z = __uint_as_float(f2tf32(b0.z - h.z));
        h.w = __uint_as_float(f2tf32(b0.w)); l.w = __uint_as_float(f2tf32(b0.w - h.w));
        *(float4*)&BH_(0, bkk, bcq<<2) = h;
        *(float4*)&BL_(0, bkk, bcq<<2) = l;
        h.x = __uint_as_float(f2tf32(b1.x)); l.x = __uint_as_float(f2tf32(b1.x - h.x));
        h.y = __uint_as_float(f2tf32(b1.y)); l.y = __uint_as_float(f2tf32(b1.y - h.y));
        h.z = __uint_as_float(f2tf32(b1.z)); l.z = __uint_as_float(f2tf32(b1.z - h.z));
        h.w = __uint_as_float(f2tf32(b1.w)); l.w = __uint_as_float(f2tf32(b1.w - h.w));
        *(float4*)&BH_(0, bkk + 8, bcq<<2) = h;
        *(float4*)&BL_(0, bkk + 8, bcq<<2) = l;
        __syncthreads();
    }

    int T = K >> 4;
    for (int kt = 0; kt < T; kt++) {
        int cur = kt & 1, nxt = cur ^ 1;
        float4 a0, a1, b0, b1;
        if (kt < T - 1) {
            int k0 = (kt + 1) << 4;
            a0 = *(const float4*)(Ap0 + k0);
            a1 = *(const float4*)(Ap1 + k0);
            b0 = *(const float4*)(Bp0 + (size_t)k0*N);
            b1 = *(const float4*)(Bp1 + (size_t)k0*N);
        }
        #pragma unroll
        for (int k8 = 0; k8 < 16; k8 += 8) {
            unsigned bh[4][2], bl[4][2];
            #pragma unroll
            for (int nt = 0; nt < 4; nt++) {
                int c = wn + (nt << 3) + g;
                bh[nt][0] = __float_as_uint(BH_(cur, k8 + tg,     c));
                bh[nt][1] = __float_as_uint(BH_(cur, k8 + tg + 4, c));
                bl[nt][0] = __float_as_uint(BL_(cur, k8 + tg,     c));
                bl[nt][1] = __float_as_uint(BL_(cur, k8 + tg + 4, c));
            }
            #pragma unroll
            for (int mt = 0; mt < 4; mt++) {
                int r = wm + (mt << 4) + g;
                unsigned ah[4], al[4];
                ah[0] = __float_as_uint(AH_(cur, r,     k8 + tg));
                ah[1] = __float_as_uint(AH_(cur, r + 8, k8 + tg));
                ah[2] = __float_as_uint(AH_(cur, r,     k8 + tg + 4));
                ah[3] = __float_as_uint(AH_(cur, r + 8, k8 + tg + 4));
                al[0] = __float_as_uint(AL_(cur, r,     k8 + tg));
                al[1] = __float_as_uint(AL_(cur, r + 8, k8 + tg));
                al[2] = __float_as_uint(AL_(cur, r,     k8 + tg + 4));
                al[3] = __float_as_uint(AL_(cur, r + 8, k8 + tg + 4));
                #pragma unroll
                for (int nt = 0; nt < 4; nt++) {
                    mma_tf32(acc[mt][nt], ah, bh[nt]);
                    mma_tf32(acc[mt][nt], al, bh[nt]);
                    mma_tf32(acc[mt][nt], ah, bl[nt]);
                }
            }
        }
        if (kt < T - 1) {
            float av0[4] = {a0.x, a0.y, a0.z, a0.w};
            float av1[4] = {a1.x, a1.y, a1.z, a1.w};
            #pragma unroll
            for (int e = 0; e < 4; e++) {
                float h0 = __uint_as_float(f2tf32(av0[e]));
                float h1 = __uint_as_float(f2tf32(av1[e]));
                AH_(nxt, ar,      (akq<<2)+e) = h0;
                AL_(nxt, ar,      (akq<<2)+e) = __uint_as_float(f2tf32(av0[e] - h0));
                AH_(nxt, ar + 64, (akq<<2)+e) = h1;
                AL_(nxt, ar + 64, (akq<<2)+e) = __uint_as_float(f2tf32(av1[e] - h1));
            }
            float4 h, l;
            h.x = __uint_as_float(f2tf32(b0.x)); l.x = __uint_as_float(f2tf32(b0.x - h.x));
            h.y = __uint_as_float(f2tf32(b0.y)); l.y = __uint_as_float(f2tf32(b0.y - h.y));
            h.z = __uint_as_float(f2tf32(b0.z)); l.z = __uint_as_float(f2tf32(b0.z - h.z));
            h.w = __uint_as_float(f2tf32(b0.w)); l.w = __uint_as_float(f2tf32(b0.w - h.w));
            *(float4*)&BH_(nxt, bkk, bcq<<2) = h;
            *(float4*)&BL_(nxt, bkk, bcq<<2) = l;
            h.x = __uint_as_float(f2tf32(b1.x)); l.x = __uint_as_float(f2tf32(b1.x - h.x));
            h.y = __uint_as_float(f2tf32(b1.y)); l.y = __uint_as_float(f2tf32(b1.y - h.y));
            h.z = __uint_as_float(f2tf32(b1.z)); l.z = __uint_as_float(f2tf32(b1.z - h.z));
            h.w = __uint_as_float(f2tf32(b1.w)); l.w = __uint_as_float(f2tf32(b1.w - h.w));
            *(float4*)&BH_(nxt, bkk + 8, bcq<<2) = h;
            *(float4*)&BL_(nxt, bkk + 8, bcq<<2) = l;
            __syncthreads();
        }
    }

    // ---- epilogue ----
    #pragma unroll
    for (int mt = 0; mt < 4; mt++) {
        #pragma unroll
        for (int nt = 0; nt < 4; nt++) {
            int r0 = bm + wm + (mt << 4) + g;
            int cc = bn + wn + (nt << 3) + (tg << 1);
            float* p0 = C + (size_t)r0 * N + cc;
            float* p1 = C + (size_t)(r0 + 8) * N + cc;
            float v00 = acc[mt][nt][0], v01 = acc[mt][nt][1];
            float v10 = acc[mt][nt][2], v11 = acc[mt][nt][3];
            if (EPI == 0) {
                *(float2*)p0 = make_float2(v00, v01);
                *(float2*)p1 = make_float2(v10, v11);
            } else if (EPI == 2) {
                float b0v = bias[cc], b1v = bias[cc + 1];
                float z;
                z = v00 + b0v; v00 = z > 0.f ? z : 0.01f*z;
                z = v01 + b1v; v01 = z > 0.f ? z : 0.01f*z;
                z = v10 + b0v; v10 = z > 0.f ? z : 0.01f*z;
                z = v11 + b1v; v11 = z > 0.f ? z : 0.01f*z;
                *(float2*)p0 = make_float2(v00, v01);
                *(float2*)p1 = make_float2(v10, v11);
            } else if (EPI == 3) {
                float b0v = bias[cc], b1v = bias[cc + 1];
                float2 o0 = *(float2*)p0, o1 = *(float2*)p1;
                o0.x += v00 + b0v; o0.y += v01 + b1v;
                o1.x += v10 + b0v; o1.y += v11 + b1v;
                *(float2*)p0 = o0;
                *(float2*)p1 = o1;
            } else if (EPI == 4) {
                float2 o0 = *(float2*)p0, o1 = *(float2*)p1;
                o0.x += v00; o0.y += v01;
                o1.x += v10; o1.y += v11;
                *(float2*)p0 = o0;
                *(float2*)p1 = o1;
            }
        }
    }
}

// ---------------- KV mean-pool into NATURAL [B,H,NB,DH] layout ----------------
__global__ void pool_kernel(const float* __restrict__ k, const float* __restrict__ v,
                            float* __restrict__ kc, float* __restrict__ vc)
{
    int wid = (blockIdx.x * blockDim.x + threadIdx.x) >> 5;  // [0, B*H*NB)
    int lane = threadIdx.x & 31;
    if (wid >= BB*HH*NB) return;
    int n = wid % NB;
    int h = (wid / NB) % HH;
    int b = wid / (NB*HH);
    float sk = 0.f, sv = 0.f;
    #pragma unroll
    for (int c = 0; c < 4; c++) {
        size_t idx = ((size_t)(b*SS + n*4 + c)*HH + h)*DHH + lane;
        sk += k[idx]; sv += v[idx];
    }
    size_t oidx = (((size_t)(b*HH + h))*NB + n)*DHH + lane;   // coalesced over lane
    kc[oidx] = sk * 0.25f;
    vc[oidx] = sv * 0.25f;
}

// ---------------- fused NSA attention: one THREAD per (b,h,t), f32x2 packed ----
__global__ void __launch_bounds__(256) nsa_attn_kernel(
    const float* __restrict__ q, const float* __restrict__ k, const float* __restrict__ v,
    const float* __restrict__ kc, const float* __restrict__ vc,
    const float* __restrict__ g, float* __restrict__ o)
{
    __shared__ float kcs[64][32];   // [n][dh]
    __shared__ float vcs[64][32];

    int tid   = threadIdx.x;
    int qtile = (NQT - 1) - (blockIdx.x & (NQT - 1));  // heavy first
    int h     = (blockIdx.x / NQT) & (HH - 1);
    int b     = blockIdx.x / (NQT * HH);
    int t     = qtile * QT + tid;

    const float SCALE = 0.17677669529663687f;  // 32^-0.5
    ull qp[16];                                 // q packed over dh: qp[j] = (q[2j], q[2j+1]) * scale
    {
        const float4* qr = (const float4*)(q + ((size_t)(b*SS + t)*HH + h)*DHH);
        #pragma unroll
        for (int i = 0; i < 8; i++) {
            float4 f = qr[i];
            qp[2*i]   = pk2(f.x * SCALE, f.y * SCALE);
            qp[2*i+1] = pk2(f.z * SCALE, f.w * SCALE);
        }
    }

    int own = t >> 2;
    const float* kcb = kc + ((size_t)(b*HH + h))*NB*DHH;
    const float* vcb = vc + ((size_t)(b*HH + h))*NB*DHH;

    float Ml = -INFINITY, Z = 0.f;
    ull av2[16];                                // output accumulator packed over dh
    #pragma unroll
    for (int j = 0; j < 16; j++) av2[j] = 0ull; // bits 0 == (0.f, 0.f)
    float bval = -INFINITY; int bidx = NB;

    for (int tile = 0; tile <= qtile; tile++) {
        int n0 = tile << 6;
        if (tile) __syncthreads();
        #pragma unroll
        for (int i = 0; i < 2; i++) {
            int idx = tid + (i << 8);           // 512 float4 per array
            int row = idx >> 3, c4 = idx & 7;
            *(float4*)&kcs[row][c4 << 2] = *(const float4*)(kcb + (size_t)(n0 + row)*DHH + (c4 << 2));
            *(float4*)&vcs[row][c4 << 2] = *(const float4*)(vcb + (size_t)(n0 + row)*DHH + (c4 << 2));
        }
        __syncthreads();

        int lim = (tile == qtile) ? ((tid + 1) >> 2) : 64;

        for (int n4 = 0; n4 < 64; n4 += 4) {
            if (n4 >= lim) break;
            // 4 packed dot-products, one per block row
            ull a0 = 0, a1 = 0, a2 = 0, a3 = 0;
            #pragma unroll
            for (int j = 0; j < 8; j++) {
                ulonglong2 k0 = *(const ulonglong2*)&kcs[n4+0][j << 2];
                ulonglong2 k1 = *(const ulonglong2*)&kcs[n4+1][j << 2];
                ulonglong2 k2 = *(const ulonglong2*)&kcs[n4+2][j << 2];
                ulonglong2 k3 = *(const ulonglong2*)&kcs[n4+3][j << 2];
                a0 = fma2(qp[2*j], k0.x, a0); a0 = fma2(qp[2*j+1], k0.y, a0);
                a1 = fma2(qp[2*j], k1.x, a1); a1 = fma2(qp[2*j+1], k1.y, a1);
                a2 = fma2(qp[2*j], k2.x, a2); a2 = fma2(qp[2*j+1], k2.y, a2);
                a3 = fma2(qp[2*j], k3.x, a3); a3 = fma2(qp[2*j+1], k3.y, a3);
            }
            float lo, hi;
            upk2(lo, hi, a0); float s0 = lo + hi;
            upk2(lo, hi, a1); float s1 = lo + hi;
            upk2(lo, hi, a2); float s2 = lo + hi;
            upk2(lo, hi, a3); float s3 = lo + hi;

            if (n4 + 1 >= lim) s1 = -INFINITY;
            if (n4 + 2 >= lim) s2 = -INFINITY;
            if (n4 + 3 >= lim) s3 = -INFINITY;

            int gn = n0 + n4;
            if (gn + 0 != own && s0 > bval) { bval = s0; bidx = gn + 0; }
            if (gn + 1 != own && s1 > bval) { bval = s1; bidx = gn + 1; }
            if (gn + 2 != own && s2 > bval) { bval = s2; bidx = gn + 2; }
            if (gn + 3 != own && s3 > bval) { bval = s3; bidx = gn + 3; }

            float m4 = fmaxf(fmaxf(s0, s1), fmaxf(s2, s3));
            if (m4 > Ml) {
                float r = __expf(Ml - m4);
                ull rr = pk2(r, r);
                Z *= r;
                #pragma unroll
                for (int j = 0; j < 16; j++) av2[j] = mul2(av2[j], rr);
                Ml = m4;
            }
            float p0 = __expf(s0 - Ml);
            float p1 = __expf(s1 - Ml);
            float p2 = __expf(s2 - Ml);
            float p3 = __expf(s3 - Ml);
            Z += (p0 + p1) + (p2 + p3);
            ull pp0 = pk2(p0, p0), pp1 = pk2(p1, p1);
            ull pp2 = pk2(p2, p2), pp3 = pk2(p3, p3);
            #pragma unroll
            for (int j = 0; j < 8; j++) {
                ulonglong2 v0 = *(const ulonglong2*)&vcs[n4+0][j << 2];
                ulonglong2 v1 = *(const ulonglong2*)&vcs[n4+1][j << 2];
                ulonglong2 v2 = *(const ulonglong2*)&vcs[n4+2][j << 2];
                ulonglong2 v3 = *(const ulonglong2*)&vcs[n4+3][j << 2];
                av2[2*j]   = fma2(pp0, v0.x, av2[2*j]);
                av2[2*j+1] = fma2(pp0, v0.y, av2[2*j+1]);
                av2[2*j]   = fma2(pp1, v1.x, av2[2*j]);
                av2[2*j+1] = fma2(pp1, v1.y, av2[2*j+1]);
                av2[2*j]   = fma2(pp2, v2.x, av2[2*j]);
                av2[2*j+1] = fma2(pp2, v2.y, av2[2*j+1]);
                av2[2*j]   = fma2(pp3, v3.x, av2[2*j]);
                av2[2*j+1] = fma2(pp3, v3.y, av2[2*j+1]);
            }
        }
    }

    if (bval == -INFINITY) bidx = (own == 0) ? 1 : 0;

    const float* gr = g + (size_t)(b*SS + t)*24;
    float g0 = gr[h], g1 = gr[8 + h], g2 = gr[16 + h];

    // scale compressed branch by g0/Z
    float invZ = (Z > 0.f) ? (1.f / Z) : 0.f;
    {
        ull c0p = pk2(g0 * invZ, g0 * invZ);
        #pragma unroll
        for (int j = 0; j < 16; j++) av2[j] = mul2(av2[j], c0p);
    }

    // ---- selection branch: blocks {own, bidx}, 8 keys, mask pos<=t ----
    float sc[8];
    float smax = -INFINITY;
    #pragma unroll
    for (int e = 0; e < 8; e++) {
        int pos = ((e < 4) ? own : bidx) * 4 + (e & 3);
        const ulonglong2* kr = (const ulonglong2*)(k + ((size_t)(b*SS + pos)*HH + h)*DHH);
        ull acc = 0;
        #pragma unroll
        for (int i = 0; i < 8; i++) {
            ulonglong2 kk2 = kr[i];
            acc = fma2(qp[2*i], kk2.x, acc);
            acc = fma2(qp[2*i+1], kk2.y, acc);
        }
        float lo, hi; upk2(lo, hi, acc);
        float s = lo + hi;
        s = (pos <= t) ? s : -INFINITY;
        sc[e] = s;
        smax = fmaxf(smax, s);
    }
    float zf = 0.f;
    #pragma unroll
    for (int e = 0; e < 8; e++) { sc[e] = __expf(sc[e] - smax); zf += sc[e]; }
    float c1 = g1 / zf;
    #pragma unroll
    for (int e = 0; e < 8; e++) {
        int pos = ((e < 4) ? own : bidx) * 4 + (e & 3);
        ull ww = pk2(sc[e] * c1, sc[e] * c1);
        const ulonglong2* vr = (const ulonglong2*)(v + ((size_t)(b*SS + pos)*HH + h)*DHH);
        #pragma unroll
        for (int i = 0; i < 8; i++) {
            ulonglong2 vv = vr[i];
            av2[2*i]   = fma2(ww, vv.x, av2[2*i]);
            av2[2*i+1] = fma2(ww, vv.y, av2[2*i+1]);
        }
    }

    // ---- sliding-window branch: keys {t-1, t} ----
    int tp = (t > 0) ? t - 1 : 0;
    float s1w, s0w;
    {
        const ulonglong2* kr1 = (const ulonglong2*)(k + ((size_t)(b*SS + t )*HH + h)*DHH);
        const ulonglong2* kr0 = (const ulonglong2*)(k + ((size_t)(b*SS + tp)*HH + h)*DHH);
        ull ac1 = 0, ac0 = 0;
        #pragma unroll
        for (int i = 0; i < 8; i++) {
            ulonglong2 k1 = kr1[i], k0 = kr0[i];
            ac1 = fma2(qp[2*i], k1.x, ac1); ac1 = fma2(qp[2*i+1], k1.y, ac1);
            ac0 = fma2(qp[2*i], k0.x, ac0); ac0 = fma2(qp[2*i+1], k0.y, ac0);
        }
        float lo, hi;
        upk2(lo, hi, ac1); s1w = lo + hi;
        upk2(lo, hi, ac0); s0w = lo + hi;
    }
    if (t == 0) s0w = -INFINITY;
    float wm = fmaxf(s0w, s1w);
    float p0w = __expf(s0w - wm), p1w = __expf(s1w - wm);
    float c2 = g2 / (p0w + p1w);
    {
        ull w0p = pk2(p0w * c2, p0w * c2);
        ull w1p = pk2(p1w * c2, p1w * c2);
        const ulonglong2* vr1 = (const ulonglong2*)(v + ((size_t)(b*SS + t )*HH + h)*DHH);
        const ulonglong2* vr0 = (const ulonglong2*)(v + ((size_t)(b*SS + tp)*HH + h)*DHH);
        #pragma unroll
        for (int i = 0; i < 8; i++) {
            ulonglong2 v1 = vr1[i], v0 = vr0[i];
            av2[2*i]   = fma2(w1p, v1.x, fma2(w0p, v0.x, av2[2*i]));
            av2[2*i+1] = fma2(w1p, v1.y, fma2(w0p, v0.y, av2[2*i+1]));
        }
    }

    // write out (packed pairs map directly to contiguous dh)
    ulonglong2* orow = (ulonglong2*)(o + ((size_t)(b*SS + t)*HH + h)*DHH);
    #pragma unroll
    for (int j = 0; j < 8; j++) {
        ulonglong2 w2;
        w2.x = av2[2*j]; w2.y = av2[2*j+1];
        orow[j] = w2;
    }
}

// ---------------- host orchestration ----------------
extern "C" void kernel_launch(void* const* d_in, const int* in_sizes, int n_in,
                              void* d_out, int out_size)
{
    const float* x_in   = (const float*)d_in[0];
    const float* ln_a_g = (const float*)d_in[1];
    const float* ln_a_b = (const float*)d_in[2];
    const float* Wq     = (const float*)d_in[3];
    const float* Wk     = (const float*)d_in[4];
    const float* Wv     = (const float*)d_in[5];
    const float* Wg     = (const float*)d_in[6];
    const float* Wo     = (const float*)d_in[7];
    const float* ln_f_g = (const float*)d_in[8];
    const float* ln_f_b = (const float*)d_in[9];
    const float* W1     = (const float*)d_in[10];
    const float* b1     = (const float*)d_in[11];
    const float* W2     = (const float*)d_in[12];
    const float* b2     = (const float*)d_in[13];
    float* x = (float*)d_out;

    float *ph, *pq, *pk, *pv, *po, *pg, *pkc, *pvc, *pmid;
    cudaGetSymbolAddress((void**)&ph,   g_h);
    cudaGetSymbolAddress((void**)&pq,   g_q);
    cudaGetSymbolAddress((void**)&pk,   g_k);
    cudaGetSymbolAddress((void**)&pv,   g_v);
    cudaGetSymbolAddress((void**)&po,   g_o);
    cudaGetSymbolAddress((void**)&pg,   g_g);
    cudaGetSymbolAddress((void**)&pkc,  g_kc);
    cudaGetSymbolAddress((void**)&pvc,  g_vc);
    cudaGetSymbolAddress((void**)&pmid, g_mid);

    cudaFuncSetAttribute(mma_gemm_kernel<0, true>,  cudaFuncAttributeMaxDynamicSharedMemorySize, GEMM_SMEM_BYTES);
    cudaFuncSetAttribute(mma_gemm_kernel<4, false>, cudaFuncAttributeMaxDynamicSharedMemorySize, GEMM_SMEM_BYTES);
    cudaFuncSetAttribute(mma_gemm_kernel<2, false>, cudaFuncAttributeMaxDynamicSharedMemorySize, GEMM_SMEM_BYTES);
    cudaFuncSetAttribute(mma_gemm_kernel<3, false>, cudaFuncAttributeMaxDynamicSharedMemorySize, GEMM_SMEM_BYTES);

    cudaMemcpyAsync(x, x_in, (size_t)BSD * sizeof(float), cudaMemcpyDeviceToDevice, 0);

    for (int l = 0; l < 2; l++) {
        for (int j2 = 0; j2 < 2; j2++) {
            int li = l*2 + j2;
            ln_kernel<<<BS/8, 256>>>(x, ln_a_g + li*DIMM, ln_a_b + li*DIMM, ph);
            mma_gemm_kernel<0, true><<<dim3(2, 64, 3), 256, GEMM_SMEM_BYTES>>>(
                ph,
                Wq + (size_t)li*DIMM*DIMM, Wk + (size_t)li*DIMM*DIMM, Wv + (size_t)li*DIMM*DIMM,
                nullptr, pq, pk, pv, BS, DIMM, DIMM);
            gate_gemm_kernel<<<dim3(1, BS/64), 256>>>(ph, Wg + (size_t)li*DIMM*24, pg, BS, 24, DIMM);
            pool_kernel<<<(BB*HH*NB*32)/256, 256>>>(pk, pv, pkc, pvc);
            nsa_attn_kernel<<<BB*HH*NQT, 256>>>(pq, pk, pv, pkc, pvc, pg, po);
            mma_gemm_kernel<4, false><<<dim3(2, 64), 256, GEMM_SMEM_BYTES>>>(
                po, Wo + (size_t)li*DIMM*DIMM, nullptr, nullptr,
                nullptr, x, nullptr, nullptr, BS, DIMM, DIMM);
        }
        ln_kernel<<<BS/8, 256>>>(x, ln_f_g + l*DIMM, ln_f_b + l*DIMM, ph);
        mma_gemm_kernel<2, false><<<dim3(4, 64), 256, GEMM_SMEM_BYTES>>>(
            ph, W1 + (size_t)l*DIMM*512, nullptr, nullptr,
            b1 + l*512, pmid, nullptr, nullptr, BS, 512, DIMM);
        mma_gemm_kernel<3, false><<<dim3(2, 64), 256, GEMM_SMEM_BYTES>>>(
            pmid, W2 + (size_t)l*512*DIMM, nullptr, nullptr,
            b2 + l*DIMM, x, nullptr, nullptr, BS, DIMM, 512);
    }
}

// round 9
// speedup vs baseline: 1.5161x; 1.0580x over previous
#include <cuda_runtime.h>
#include <math.h>

#define BB   4
#define SS   2048
#define HH   8
#define DHH  32
#define DIMM 256
#define NB   512          // SS / 4 compressed blocks
#define BS   (BB*SS)      // 8192 rows
#define BSD  (BS*DIMM)    // 2097152 floats
#define QT2  128          // queries per attn block (pair-per-query)
#define NQT2 (SS/QT2)     // 16 qtiles

typedef unsigned long long ull;

// ---------------- scratch (static device buffers; no allocs) ----------------
__device__ float g_h  [BSD];
__device__ float g_q  [BSD];
__device__ float g_k  [BSD];
__device__ float g_v  [BSD];
__device__ float g_o  [BSD];
__device__ float g_g  [BS*24];
__device__ float g_kc [BB*HH*NB*DHH];
__device__ float g_vc [BB*HH*NB*DHH];
__device__ float g_mid[BS*512];

__device__ __forceinline__ unsigned f2tf32(float x) {
    unsigned u; asm("cvt.rna.tf32.f32 %0, %1;" : "=r"(u) : "f"(x)); return u;
}

__device__ __forceinline__ void mma_tf32(float* c, const unsigned* a, const unsigned* b) {
    asm volatile(
        "mma.sync.aligned.m16n8k8.row.col.f32.tf32.tf32.f32 "
        "{%0,%1,%2,%3}, {%4,%5,%6,%7}, {%8,%9}, {%0,%1,%2,%3};"
        : "+f"(c[0]), "+f"(c[1]), "+f"(c[2]), "+f"(c[3])
        : "r"(a[0]), "r"(a[1]), "r"(a[2]), "r"(a[3]), "r"(b[0]), "r"(b[1]));
}

// ---------------- packed f32x2 helpers ----------------
__device__ __forceinline__ ull pk2(float lo, float hi) {
    ull r; asm("mov.b64 %0, {%1,%2};" : "=l"(r) : "f"(lo), "f"(hi)); return r;
}
__device__ __forceinline__ void upk2(float& lo, float& hi, ull v) {
    asm("mov.b64 {%0,%1}, %2;" : "=f"(lo), "=f"(hi) : "l"(v));
}
__device__ __forceinline__ ull fma2(ull a, ull b, ull c) {
    ull d; asm("fma.rn.f32x2 %0, %1, %2, %3;" : "=l"(d) : "l"(a), "l"(b), "l"(c)); return d;
}
__device__ __forceinline__ ull mul2(ull a, ull b) {
    ull d; asm("mul.rn.f32x2 %0, %1, %2;" : "=l"(d) : "l"(a), "l"(b)); return d;
}
__device__ __forceinline__ float ex2(float x) {
    float y; asm("ex2.approx.f32 %0, %1;" : "=f"(y) : "f"(x)); return y;
}

// ---------------- LayerNorm: one warp per row of 256 ----------------
__global__ void ln_kernel(const float* __restrict__ x, const float* __restrict__ gw,
                          const float* __restrict__ bw, float* __restrict__ out)
{
    int warp = (blockIdx.x * blockDim.x + threadIdx.x) >> 5;
    int lane = threadIdx.x & 31;
    if (warp >= BS) return;
    const float* xr = x + (size_t)warp * DIMM;
    float vbuf[8];
    float s = 0.f;
    #pragma unroll
    for (int i = 0; i < 8; i++) { vbuf[i] = xr[lane + i*32]; s += vbuf[i]; }
    #pragma unroll
    for (int o = 16; o > 0; o >>= 1) s += __shfl_xor_sync(~0u, s, o);
    float m = s * (1.f/256.f);
    float sq = 0.f;
    #pragma unroll
    for (int i = 0; i < 8; i++) { float d = vbuf[i] - m; sq += d*d; }
    #pragma unroll
    for (int o = 16; o > 0; o >>= 1) sq += __shfl_xor_sync(~0u, sq, o);
    float rstd = rsqrtf(sq * (1.f/256.f) + 1e-5f);
    float* orow = out + (size_t)warp * DIMM;
    #pragma unroll
    for (int i = 0; i < 8; i++) {
        int c = lane + i*32;
        orow[c] = (vbuf[i] - m) * rstd * gw[c] + bw[c];
    }
}

// ---------------- small GEMM for gate (N=24), sigmoid epilogue ----------------
__global__ void __launch_bounds__(256) gate_gemm_kernel(
    const float* __restrict__ A, const float* __restrict__ B,
    float* __restrict__ C, int M, int N, int K)
{
    __shared__ float As[16][65];
    __shared__ float Bs[16][65];
    int tid = threadIdx.x;
    int tx = tid & 15, ty = tid >> 4;
    int bm = blockIdx.y << 6, bn = blockIdx.x << 6;
    float acc[4][4];
    #pragma unroll
    for (int i = 0; i < 4; i++)
        #pragma unroll
        for (int j = 0; j < 4; j++) acc[i][j] = 0.f;

    for (int k0 = 0; k0 < K; k0 += 16) {
        #pragma unroll
        for (int i = 0; i < 4; i++) {
            int e = tid + (i << 8);
            int r = e >> 4, kk = e & 15;
            As[kk][r] = A[(size_t)(bm + r)*K + k0 + kk];
        }
        #pragma unroll
        for (int i = 0; i < 4; i++) {
            int e = tid + (i << 8);
            int kk = e >> 6, c = e & 63;
            Bs[kk][c] = (bn + c < N) ? B[(size_t)(k0 + kk)*N + bn + c] : 0.f;
        }
        __syncthreads();
        #pragma unroll
        for (int kk = 0; kk < 16; kk++) {
            float a[4], bb[4];
            #pragma unroll
            for (int i = 0; i < 4; i++) a[i] = As[kk][(ty<<2)+i];
            #pragma unroll
            for (int j = 0; j < 4; j++) bb[j] = Bs[kk][(tx<<2)+j];
            #pragma unroll
            for (int i = 0; i < 4; i++)
                #pragma unroll
                for (int j = 0; j < 4; j++)
                    acc[i][j] = fmaf(a[i], bb[j], acc[i][j]);
        }
        __syncthreads();
    }
    #pragma unroll
    for (int i = 0; i < 4; i++) {
        int row = bm + (ty<<2) + i;
        #pragma unroll
        for (int j = 0; j < 4; j++) {
            int col = bn + (tx<<2) + j;
            if (col >= N) continue;
            C[(size_t)row * N + col] = 1.f / (1.f + expf(-acc[i][j]));
        }
    }
}

// ---------------- main GEMM: 3xTF32 tensor-core, 128x128 tile, BK=16 --------
#define AH_(b,r,c) sAh[((b)*128 + (r))*20 + (c)]
#define AL_(b,r,c) sAl[((b)*128 + (r))*20 + (c)]
#define BH_(b,k,c) sBh[((b)*16  + (k))*136 + (c)]
#define BL_(b,k,c) sBl[((b)*16  + (k))*136 + (c)]
#define GEMM_SMEM_BYTES ((2*128*20*2 + 2*16*136*2) * 4)

template<int EPI, bool QKV>
__global__ void __launch_bounds__(256, 2) mma_gemm_kernel(
    const float* __restrict__ A,
    const float* __restrict__ B0, const float* __restrict__ B1, const float* __restrict__ B2,
    const float* __restrict__ bias,
    float* __restrict__ C0, float* __restrict__ C1, float* __restrict__ C2,
    int M, int N, int K)
{
    extern __shared__ float sm_[];
    float* sAh = sm_;
    float* sAl = sAh + 2*128*20;
    float* sBh = sAl + 2*128*20;
    float* sBl = sBh + 2*16*136;

    const float* B = B0;
    float* C = C0;
    if (QKV) {
        if (blockIdx.z == 1)      { B = B1; C = C1; }
        else if (blockIdx.z == 2) { B = B2; C = C2; }
    }

    int tid  = threadIdx.x;
    int wid  = tid >> 5, lane = tid & 31;
    int g    = lane >> 2, tg = lane & 3;
    int wm   = (wid >> 2) << 6;
    int wn   = (wid & 3) << 5;
    int bm   = blockIdx.y << 7, bn = blockIdx.x << 7;

    int ar  = tid >> 2, akq = tid & 3;
    const float* Ap0 = A + (size_t)(bm + ar)*K + (akq << 2);
    const float* Ap1 = A + (size_t)(bm + 64 + ar)*K + (akq << 2);
    int bkk = tid >> 5, bcq = tid & 31;
    const float* Bp0 = B + (size_t)bkk*N + bn + (bcq << 2);
    const float* Bp1 = B + (size_t)(bkk + 8)*N + bn + (bcq << 2);

    float acc[4][4][4];
    #pragma unroll
    for (int mt = 0; mt < 4; mt++)
        #pragma unroll
        for (int nt = 0; nt < 4; nt++)
            #pragma unroll
            for (int r = 0; r < 4; r++) acc[mt][nt][r] = 0.f;

    // ---- prologue: tile 0 -> buffer 0 ----
    {
        float4 a0 = *(const float4*)Ap0;
        float4 a1 = *(const float4*)Ap1;
        float4 b0 = *(const float4*)Bp0;
        float4 b1 = *(const float4*)Bp1;
        float av0[4] = {a0.x, a0.y, a0.z, a0.w};
        float av1[4] = {a1.x, a1.y, a1.z, a1.w};
        #pragma unroll
        for (int e = 0; e < 4; e++) {
            float h0 = __uint_as_float(f2tf32(av0[e]));
            float h1 = __uint_as_float(f2tf32(av1[e]));
            AH_(0, ar,      (akq<<2)+e) = h0;
            AL_(0, ar,      (akq<<2)+e) = __uint_as_float(f2tf32(av0[e] - h0));
            AH_(0, ar + 64, (akq<<2)+e) = h1;
            AL_(0, ar + 64, (akq<<2)+e) = __uint_as_float(f2tf32(av1[e] - h1));
        }
        float4 h, l;
        h.x = __uint_as_float(f2tf32(b0.x)); l.x = __uint_as_float(f2tf32(b0.x - h.x));
        h.y = __uint_as_float(f2tf32(b0.y)); l.y = __uint_as_float(f2tf32(b0.y - h.y));
        h.z = __uint_as_float(f2tf32(b0.z)); l.z = __uint_as_float(f2tf32(b0.z - h.z));
        h.w = __uint_as_float(f2tf32(b0.w)); l.w = __uint_as_float(f2tf32(b0.w - h.w));
        *(float4*)&BH_(0, bkk, bcq<<2) = h;
        *(float4*)&BL_(0, bkk, bcq<<2) = l;
        h.x = __uint_as_float(f2tf32(b1.x)); l.x = __uint_as_float(f2tf32(b1.x - h.x));
        h.y = __uint_as_float(f2tf32(b1.y)); l.y = __uint_as_float(f2tf32(b1.y - h.y));
        h.z = __uint_as_float(f2tf32(b1.z)); l.z = __uint_as_float(f2tf32(b1.z - h.z));
        h.w = __uint_as_float(f2tf32(b1.w)); l.w = __uint_as_float(f2tf32(b1.w - h.w));
        *(float4*)&BH_(0, bkk + 8, bcq<<2) = h;
        *(float4*)&BL_(0, bkk + 8, bcq<<2) = l;
        __syncthreads();
    }

    int T = K >> 4;
    for (int kt = 0; kt < T; kt++) {
        int cur = kt & 1, nxt = cur ^ 1;
        float4 a0, a1, b0, b1;
        if (kt < T - 1) {
            int k0 = (kt + 1) << 4;
            a0 = *(const float4*)(Ap0 + k0);
            a1 = *(const float4*)(Ap1 + k0);
            b0 = *(const float4*)(Bp0 + (size_t)k0*N);
            b1 = *(const float4*)(Bp1 + (size_t)k0*N);
        }
        #pragma unroll
        for (int k8 = 0; k8 < 16; k8 += 8) {
            unsigned bh[4][2], bl[4][2];
            #pragma unroll
            for (int nt = 0; nt < 4; nt++) {
                int c = wn + (nt << 3) + g;
                bh[nt][0] = __float_as_uint(BH_(cur, k8 + tg,     c));
                bh[nt][1] = __float_as_uint(BH_(cur, k8 + tg + 4, c));
                bl[nt][0] = __float_as_uint(BL_(cur, k8 + tg,     c));
                bl[nt][1] = __float_as_uint(BL_(cur, k8 + tg + 4, c));
            }
            #pragma unroll
            for (int mt = 0; mt < 4; mt++) {
                int r = wm + (mt << 4) + g;
                unsigned ah[4], al[4];
                ah[0] = __float_as_uint(AH_(cur, r,     k8 + tg));
                ah[1] = __float_as_uint(AH_(cur, r + 8, k8 + tg));
                ah[2] = __float_as_uint(AH_(cur, r,     k8 + tg + 4));
                ah[3] = __float_as_uint(AH_(cur, r + 8, k8 + tg + 4));
                al[0] = __float_as_uint(AL_(cur, r,     k8 + tg));
                al[1] = __float_as_uint(AL_(cur, r + 8, k8 + tg));
                al[2] = __float_as_uint(AL_(cur, r,     k8 + tg + 4));
                al[3] = __float_as_uint(AL_(cur, r + 8, k8 + tg + 4));
                #pragma unroll
                for (int nt = 0; nt < 4; nt++) {
                    mma_tf32(acc[mt][nt], ah, bh[nt]);
                    mma_tf32(acc[mt][nt], al, bh[nt]);
                    mma_tf32(acc[mt][nt], ah, bl[nt]);
                }
            }
        }
        if (kt < T - 1) {
            float av0[4] = {a0.x, a0.y, a0.z, a0.w};
            float av1[4] = {a1.x, a1.y, a1.z, a1.w};
            #pragma unroll
            for (int e = 0; e < 4; e++) {
                float h0 = __uint_as_float(f2tf32(av0[e]));
                float h1 = __uint_as_float(f2tf32(av1[e]));
                AH_(nxt, ar,      (akq<<2)+e) = h0;
                AL_(nxt, ar,      (akq<<2)+e) = __uint_as_float(f2tf32(av0[e] - h0));
                AH_(nxt, ar + 64, (akq<<2)+e) = h1;
                AL_(nxt, ar + 64, (akq<<2)+e) = __uint_as_float(f2tf32(av1[e] - h1));
            }
            float4 h, l;
            h.x = __uint_as_float(f2tf32(b0.x)); l.x = __uint_as_float(f2tf32(b0.x - h.x));
            h.y = __uint_as_float(f2tf32(b0.y)); l.y = __uint_as_float(f2tf32(b0.y - h.y));
            h.z = __uint_as_float(f2tf32(b0.z)); l.z = __uint_as_float(f2tf32(b0.z - h.z));
            h.w = __uint_as_float(f2tf32(b0.w)); l.w = __uint_as_float(f2tf32(b0.w - h.w));
            *(float4*)&BH_(nxt, bkk, bcq<<2) = h;
            *(float4*)&BL_(nxt, bkk, bcq<<2) = l;
            h.x = __uint_as_float(f2tf32(b1.x)); l.x = __uint_as_float(f2tf32(b1.x - h.x));
            h.y = __uint_as_float(f2tf32(b1.y)); l.y = __uint_as_float(f2tf32(b1.y - h.y));
            h.z = __uint_as_float(f2tf32(b1.z)); l.z = __uint_as_float(f2tf32(b1.z - h.z));
            h.w = __uint_as_float(f2tf32(b1.w)); l.w = __uint_as_float(f2tf32(b1.w - h.w));
            *(float4*)&BH_(nxt, bkk + 8, bcq<<2) = h;
            *(float4*)&BL_(nxt, bkk + 8, bcq<<2) = l;
            __syncthreads();
        }
    }

    // ---- epilogue ----
    #pragma unroll
    for (int mt = 0; mt < 4; mt++) {
        #pragma unroll
        for (int nt = 0; nt < 4; nt++) {
            int r0 = bm + wm + (mt << 4) + g;
            int cc = bn + wn + (nt << 3) + (tg << 1);
            float* p0 = C + (size_t)r0 * N + cc;
            float* p1 = C + (size_t)(r0 + 8) * N + cc;
            float v00 = acc[mt][nt][0], v01 = acc[mt][nt][1];
            float v10 = acc[mt][nt][2], v11 = acc[mt][nt][3];
            if (EPI == 0) {
                *(float2*)p0 = make_float2(v00, v01);
                *(float2*)p1 = make_float2(v10, v11);
            } else if (EPI == 2) {
                float b0v = bias[cc], b1v = bias[cc + 1];
                float z;
                z = v00 + b0v; v00 = z > 0.f ? z : 0.01f*z;
                z = v01 + b1v; v01 = z > 0.f ? z : 0.01f*z;
                z = v10 + b0v; v10 = z > 0.f ? z : 0.01f*z;
                z = v11 + b1v; v11 = z > 0.f ? z : 0.01f*z;
                *(float2*)p0 = make_float2(v00, v01);
                *(float2*)p1 = make_float2(v10, v11);
            } else if (EPI == 3) {
                float b0v = bias[cc], b1v = bias[cc + 1];
                float2 o0 = *(float2*)p0, o1 = *(float2*)p1;
                o0.x += v00 + b0v; o0.y += v01 + b1v;
                o1.x += v10 + b0v; o1.y += v11 + b1v;
                *(float2*)p0 = o0;
                *(float2*)p1 = o1;
            } else if (EPI == 4) {
                float2 o0 = *(float2*)p0, o1 = *(float2*)p1;
                o0.x += v00; o0.y += v01;
                o1.x += v10; o1.y += v11;
                *(float2*)p0 = o0;
                *(float2*)p1 = o1;
            }
        }
    }
}

// ---------------- KV mean-pool into NATURAL [B,H,NB,DH] layout ----------------
__global__ void pool_kernel(const float* __restrict__ k, const float* __restrict__ v,
                            float* __restrict__ kc, float* __restrict__ vc)
{
    int wid = (blockIdx.x * blockDim.x + threadIdx.x) >> 5;  // [0, B*H*NB)
    int lane = threadIdx.x & 31;
    if (wid >= BB*HH*NB) return;
    int n = wid % NB;
    int h = (wid / NB) % HH;
    int b = wid / (NB*HH);
    float sk = 0.f, sv = 0.f;
    #pragma unroll
    for (int c = 0; c < 4; c++) {
        size_t idx = ((size_t)(b*SS + n*4 + c)*HH + h)*DHH + lane;
        sk += k[idx]; sv += v[idx];
    }
    size_t oidx = (((size_t)(b*HH + h))*NB + n)*DHH + lane;
    kc[oidx] = sk * 0.25f;
    vc[oidx] = sv * 0.25f;
}

// ---------------- fused NSA attention: 2 threads per query (half-dh each) ----
// Block: 256 threads = 128 queries. Grid: BB*HH*NQT2 = 512 blocks.
// KV tiles of 32 pooled blocks (8 KB smem). Scores in log2 domain (scale*log2e
// folded into q) -> single ex2.approx per exp; monotone => identical top-1.
__global__ void __launch_bounds__(256) nsa_attn_kernel(
    const float* __restrict__ q, const float* __restrict__ k, const float* __restrict__ v,
    const float* __restrict__ kc, const float* __restrict__ vc,
    const float* __restrict__ g, float* __restrict__ o)
{
    __shared__ float kcs[32][32];   // [n][dh]
    __shared__ float vcs[32][32];

    int tid   = threadIdx.x;
    int qtile = (NQT2 - 1) - (blockIdx.x & (NQT2 - 1));  // heavy first
    int h     = (blockIdx.x >> 4) & (HH - 1);
    int b     = blockIdx.x >> 7;
    int qi    = tid >> 1;
    int half  = tid & 1;
    int t     = qtile * QT2 + qi;
    unsigned pmask = 3u << (tid & 30);   // 2-lane pair shuffle mask

    // scale * log2(e): exp(s*scale) == exp2(dot(q*SCALE2, k))
    const float SCALE2 = 0.17677669529663687f * 1.4426950408889634f;
    size_t qoff = ((size_t)(b*SS + t)*HH + h)*DHH + (half << 4);
    ull qp[8];
    {
        const float4* qr = (const float4*)(q + qoff);
        #pragma unroll
        for (int i = 0; i < 4; i++) {
            float4 f = qr[i];
            qp[2*i]   = pk2(f.x * SCALE2, f.y * SCALE2);
            qp[2*i+1] = pk2(f.z * SCALE2, f.w * SCALE2);
        }
    }

    int own = t >> 2;
    const float* kcb = kc + ((size_t)(b*HH + h))*NB*DHH;
    const float* vcb = vc + ((size_t)(b*HH + h))*NB*DHH;

    float Ml = -INFINITY, Z = 0.f;
    ull av2[8];
    #pragma unroll
    for (int j = 0; j < 8; j++) av2[j] = 0ull;
    float bval = -INFINITY; int bidx = NB;

    int ldrow = tid >> 3, ldc4 = tid & 7;   // tile loader: 1 float4 per thread per array

    for (int tile = 0; tile <= qtile; tile++) {
        int n0 = tile << 5;
        if (tile) __syncthreads();
        *(float4*)&kcs[ldrow][ldc4 << 2] = *(const float4*)(kcb + (size_t)(n0 + ldrow)*DHH + (ldc4 << 2));
        *(float4*)&vcs[ldrow][ldc4 << 2] = *(const float4*)(vcb + (size_t)(n0 + ldrow)*DHH + (ldc4 << 2));
        __syncthreads();

        int lim = (tile == qtile) ? ((qi + 1) >> 2) : 32;

        for (int n4 = 0; n4 < 32; n4 += 4) {
            if (n4 >= lim) break;
            // packed half-dot products for 4 pooled blocks
            ull a0 = 0, a1 = 0, a2 = 0, a3 = 0;
            const ulonglong2* k0 = (const ulonglong2*)&kcs[n4+0][half << 4];
            const ulonglong2* k1 = (const ulonglong2*)&kcs[n4+1][half << 4];
            const ulonglong2* k2 = (const ulonglong2*)&kcs[n4+2][half << 4];
            const ulonglong2* k3 = (const ulonglong2*)&kcs[n4+3][half << 4];
            #pragma unroll
            for (int j = 0; j < 4; j++) {
                ulonglong2 r0 = k0[j], r1 = k1[j], r2 = k2[j], r3 = k3[j];
                a0 = fma2(qp[2*j], r0.x, a0); a0 = fma2(qp[2*j+1], r0.y, a0);
                a1 = fma2(qp[2*j], r1.x, a1); a1 = fma2(qp[2*j+1], r1.y, a1);
                a2 = fma2(qp[2*j], r2.x, a2); a2 = fma2(qp[2*j+1], r2.y, a2);
                a3 = fma2(qp[2*j], r3.x, a3); a3 = fma2(qp[2*j+1], r3.y, a3);
            }
            float lo, hi, s0, s1, s2, s3;
            upk2(lo, hi, a0); s0 = lo + hi;
            upk2(lo, hi, a1); s1 = lo + hi;
            upk2(lo, hi, a2); s2 = lo + hi;
            upk2(lo, hi, a3); s3 = lo + hi;
            s0 += __shfl_xor_sync(pmask, s0, 1);
            s1 += __shfl_xor_sync(pmask, s1, 1);
            s2 += __shfl_xor_sync(pmask, s2, 1);
            s3 += __shfl_xor_sync(pmask, s3, 1);

            if (n4 + 1 >= lim) s1 = -INFINITY;
            if (n4 + 2 >= lim) s2 = -INFINITY;
            if (n4 + 3 >= lim) s3 = -INFINITY;

            int gn = n0 + n4;
            if (gn + 0 != own && s0 > bval) { bval = s0; bidx = gn + 0; }
            if (gn + 1 != own && s1 > bval) { bval = s1; bidx = gn + 1; }
            if (gn + 2 != own && s2 > bval) { bval = s2; bidx = gn + 2; }
            if (gn + 3 != own && s3 > bval) { bval = s3; bidx = gn + 3; }

            float m4 = fmaxf(fmaxf(s0, s1), fmaxf(s2, s3));
            if (m4 > Ml) {
                float r = ex2(Ml - m4);     // 0 on first valid group
                ull rr = pk2(r, r);
                Z *= r;
                #pragma unroll
                for (int j = 0; j < 8; j++) av2[j] = mul2(av2[j], rr);
                Ml = m4;
            }
            float p0 = ex2(s0 - Ml);
            float p1 = ex2(s1 - Ml);
            float p2 = ex2(s2 - Ml);
            float p3 = ex2(s3 - Ml);
            Z += (p0 + p1) + (p2 + p3);
            ull pp0 = pk2(p0, p0), pp1 = pk2(p1, p1);
            ull pp2 = pk2(p2, p2), pp3 = pk2(p3, p3);
            const ulonglong2* v0 = (const ulonglong2*)&vcs[n4+0][half << 4];
            const ulonglong2* v1 = (const ulonglong2*)&vcs[n4+1][half << 4];
            const ulonglong2* v2 = (const ulonglong2*)&vcs[n4+2][half << 4];
            const ulonglong2* v3 = (const ulonglong2*)&vcs[n4+3][half << 4];
            #pragma unroll
            for (int j = 0; j < 4; j++) {
                ulonglong2 w0 = v0[j], w1 = v1[j], w2 = v2[j], w3 = v3[j];
                av2[2*j]   = fma2(pp0, w0.x, av2[2*j]);
                av2[2*j+1] = fma2(pp0, w0.y, av2[2*j+1]);
                av2[2*j]   = fma2(pp1, w1.x, av2[2*j]);
                av2[2*j+1] = fma2(pp1, w1.y, av2[2*j+1]);
                av2[2*j]   = fma2(pp2, w2.x, av2[2*j]);
                av2[2*j+1] = fma2(pp2, w2.y, av2[2*j+1]);
                av2[2*j]   = fma2(pp3, w3.x, av2[2*j]);
                av2[2*j+1] = fma2(pp3, w3.y, av2[2*j+1]);
            }
        }
    }

    if (bval == -INFINITY) bidx = (own == 0) ? 1 : 0;

    const float* gr = g + (size_t)(b*SS + t)*24;
    float g0 = gr[h], g1 = gr[8 + h], g2 = gr[16 + h];

    float invZ = (Z > 0.f) ? (1.f / Z) : 0.f;
    {
        ull c0p = pk2(g0 * invZ, g0 * invZ);
        #pragma unroll
        for (int j = 0; j < 8; j++) av2[j] = mul2(av2[j], c0p);
    }

    // ---- selection branch: blocks {own, bidx}, 8 keys, mask pos<=t ----
    float sc[8];
    float smax = -INFINITY;
    #pragma unroll
    for (int e = 0; e < 8; e++) {
        int pos = ((e < 4) ? own : bidx) * 4 + (e & 3);
        const ulonglong2* kr = (const ulonglong2*)(k + ((size_t)(b*SS + pos)*HH + h)*DHH + (half << 4));
        ull acc = 0;
        #pragma unroll
        for (int i = 0; i < 4; i++) {
            ulonglong2 kk2 = kr[i];
            acc = fma2(qp[2*i], kk2.x, acc);
            acc = fma2(qp[2*i+1], kk2.y, acc);
        }
        float lo, hi; upk2(lo, hi, acc);
        float s = lo + hi;
        s += __shfl_xor_sync(pmask, s, 1);
        s = (pos <= t) ? s : -INFINITY;
        sc[e] = s;
        smax = fmaxf(smax, s);
    }
    float zf = 0.f;
    #pragma unroll
    for (int e = 0; e < 8; e++) { sc[e] = ex2(sc[e] - smax); zf += sc[e]; }
    float c1 = g1 / zf;
    #pragma unroll
    for (int e = 0; e < 8; e++) {
        int pos = ((e < 4) ? own : bidx) * 4 + (e & 3);
        ull ww = pk2(sc[e] * c1, sc[e] * c1);
        const ulonglong2* vr = (const ulonglong2*)(v + ((size_t)(b*SS + pos)*HH + h)*DHH + (half << 4));
        #pragma unroll
        for (int i = 0; i < 4; i++) {
            ulonglong2 vv = vr[i];
            av2[2*i]   = fma2(ww, vv.x, av2[2*i]);
            av2[2*i+1] = fma2(ww, vv.y, av2[2*i+1]);
        }
    }

    // ---- sliding-window branch: keys {t-1, t} ----
    int tp = (t > 0) ? t - 1 : 0;
    float s1w, s0w;
    {
        const ulonglong2* kr1 = (const ulonglong2*)(k + ((size_t)(b*SS + t )*HH + h)*DHH + (half << 4));
        const ulonglong2* kr0 = (const ulonglong2*)(k + ((size_t)(b*SS + tp)*HH + h)*DHH + (half << 4));
        ull ac1 = 0, ac0 = 0;
        #pragma unroll
        for (int i = 0; i < 4; i++) {
            ulonglong2 k1 = kr1[i], k0 = kr0[i];
            ac1 = fma2(qp[2*i], k1.x, ac1); ac1 = fma2(qp[2*i+1], k1.y, ac1);
            ac0 = fma2(qp[2*i], k0.x, ac0); ac0 = fma2(qp[2*i+1], k0.y, ac0);
        }
        float lo, hi;
        upk2(lo, hi, ac1); s1w = lo + hi;
        upk2(lo, hi, ac0); s0w = lo + hi;
        s1w += __shfl_xor_sync(pmask, s1w, 1);
        s0w += __shfl_xor_sync(pmask, s0w, 1);
    }
    if (t == 0) s0w = -INFINITY;
    float wm = fmaxf(s0w, s1w);
    float p0w = ex2(s0w - wm), p1w = ex2(s1w - wm);
    float c2 = g2 / (p0w + p1w);
    {
        ull w0p = pk2(p0w * c2, p0w * c2);
        ull w1p = pk2(p1w * c2, p1w * c2);
        const ulonglong2* vr1 = (const ulonglong2*)(v + ((size_t)(b*SS + t )*HH + h)*DHH + (half << 4));
        const ulonglong2* vr0 = (const ulonglong2*)(v + ((size_t)(b*SS + tp)*HH + h)*DHH + (half << 4));
        #pragma unroll
        for (int i = 0; i < 4; i++) {
            ulonglong2 v1 = vr1[i], v0 = vr0[i];
            av2[2*i]   = fma2(w1p, v1.x, fma2(w0p, v0.x, av2[2*i]));
            av2[2*i+1] = fma2(w1p, v1.y, fma2(w0p, v0.y, av2[2*i+1]));
        }
    }

    // write this thread's dh-half
    ulonglong2* orow = (ulonglong2*)(o + qoff);
    #pragma unroll
    for (int j = 0; j < 4; j++) {
        ulonglong2 w2;
        w2.x = av2[2*j]; w2.y = av2[2*j+1];
        orow[j] = w2;
    }
}

// ---------------- host orchestration ----------------
extern "C" void kernel_launch(void* const* d_in, const int* in_sizes, int n_in,
                              void* d_out, int out_size)
{
    const float* x_in   = (const float*)d_in[0];
    const float* ln_a_g = (const float*)d_in[1];
    const float* ln_a_b = (const float*)d_in[2];
    const float* Wq     = (const float*)d_in[3];
    const float* Wk     = (const float*)d_in[4];
    const float* Wv     = (const float*)d_in[5];
    const float* Wg     = (const float*)d_in[6];
    const float* Wo     = (const float*)d_in[7];
    const float* ln_f_g = (const float*)d_in[8];
    const float* ln_f_b = (const float*)d_in[9];
    const float* W1     = (const float*)d_in[10];
    const float* b1     = (const float*)d_in[11];
    const float* W2     = (const float*)d_in[12];
    const float* b2     = (const float*)d_in[13];
    float* x = (float*)d_out;

    float *ph, *pq, *pk, *pv, *po, *pg, *pkc, *pvc, *pmid;
    cudaGetSymbolAddress((void**)&ph,   g_h);
    cudaGetSymbolAddress((void**)&pq,   g_q);
    cudaGetSymbolAddress((void**)&pk,   g_k);
    cudaGetSymbolAddress((void**)&pv,   g_v);
    cudaGetSymbolAddress((void**)&po,   g_o);
    cudaGetSymbolAddress((void**)&pg,   g_g);
    cudaGetSymbolAddress((void**)&pkc,  g_kc);
    cudaGetSymbolAddress((void**)&pvc,  g_vc);
    cudaGetSymbolAddress((void**)&pmid, g_mid);

    cudaFuncSetAttribute(mma_gemm_kernel<0, true>,  cudaFuncAttributeMaxDynamicSharedMemorySize, GEMM_SMEM_BYTES);
    cudaFuncSetAttribute(mma_gemm_kernel<4, false>, cudaFuncAttributeMaxDynamicSharedMemorySize, GEMM_SMEM_BYTES);
    cudaFuncSetAttribute(mma_gemm_kernel<2, false>, cudaFuncAttributeMaxDynamicSharedMemorySize, GEMM_SMEM_BYTES);
    cudaFuncSetAttribute(mma_gemm_kernel<3, false>, cudaFuncAttributeMaxDynamicSharedMemorySize, GEMM_SMEM_BYTES);

    cudaMemcpyAsync(x, x_in, (size_t)BSD * sizeof(float), cudaMemcpyDeviceToDevice, 0);

    for (int l = 0; l < 2; l++) {
        for (int j2 = 0; j2 < 2; j2++) {
            int li = l*2 + j2;
            ln_kernel<<<BS/8, 256>>>(x, ln_a_g + li*DIMM, ln_a_b + li*DIMM, ph);
            mma_gemm_kernel<0, true><<<dim3(2, 64, 3), 256, GEMM_SMEM_BYTES>>>(
                ph,
                Wq + (size_t)li*DIMM*DIMM, Wk + (size_t)li*DIMM*DIMM, Wv + (size_t)li*DIMM*DIMM,
                nullptr, pq, pk, pv, BS, DIMM, DIMM);
            gate_gemm_kernel<<<dim3(1, BS/64), 256>>>(ph, Wg + (size_t)li*DIMM*24, pg, BS, 24, DIMM);
            pool_kernel<<<(BB*HH*NB*32)/256, 256>>>(pk, pv, pkc, pvc);
            nsa_attn_kernel<<<BB*HH*NQT2, 256>>>(pq, pk, pv, pkc, pvc, pg, po);
            mma_gemm_kernel<4, false><<<dim3(2, 64), 256, GEMM_SMEM_BYTES>>>(
                po, Wo + (size_t)li*DIMM*DIMM, nullptr, nullptr,
                nullptr, x, nullptr, nullptr, BS, DIMM, DIMM);
        }
        ln_kernel<<<BS/8, 256>>>(x, ln_f_g + l*DIMM, ln_f_b + l*DIMM, ph);
        mma_gemm_kernel<2, false><<<dim3(4, 64), 256, GEMM_SMEM_BYTES>>>(
            ph, W1 + (size_t)l*DIMM*512, nullptr, nullptr,
            b1 + l*512, pmid, nullptr, nullptr, BS, 512, DIMM);
        mma_gemm_kernel<3, false><<<dim3(2, 64), 256, GEMM_SMEM_BYTES>>>(
            pmid, W2 + (size_t)l*512*DIMM, nullptr, nullptr,
            b2 + l*DIMM, x, nullptr, nullptr, BS, DIMM, 512);
    }
}